// round 13
// baseline (speedup 1.0000x reference)
#include <cuda_runtime.h>
#include <math.h>

// ---------------- problem dims ----------------
#define SS    128
#define BB    64
#define EE    512
#define HH    256
#define DHH   512
#define G4H   1024
#define GD    2048
#define LDWD  2052
#define LMAXX 4
#define CC    9

#define NBE   128
#define NBD   128
#define TPB   512

typedef unsigned long long ull;

// gate-locality permutations: block owns all 4 gates of 4 units
__device__ __forceinline__ int enperm(int np) { return (((np >> 2) & 3) << 8) + ((np >> 4) << 2) + (np & 3); }
__device__ __forceinline__ int deperm(int np) { return (((np >> 2) & 3) << 9) + ((np >> 4) << 2) + (np & 3); }

// ---------------- static device scratch ----------------
__device__ float g_x   [SS*BB*EE];
__device__ float g_gxf [SS*BB*G4H];      // TRANSPOSED: [s][np][b]
__device__ float g_gxb [SS*BB*G4H];      // TRANSPOSED: [s][np][b]
__device__ float g_h   [SS*BB*DHH];      // [s][b][d] row-major
__device__ float g_wh  [SS*BB*DHH];      // [s][b][d] row-major
__device__ float g_pre0[SS*BB*GD];       // TRANSPOSED: [t][np][b]
__device__ float g_pre1[SS*BB*GD];       // TRANSPOSED: [t][np][b]
__device__ float g_dout[LMAXX*SS*BB*DHH];// [lvl][t][b][u]
__device__ float g_hencT[2*2*HH*BB];     // [p][dir][u][b]
__device__ float g_cencT[2*HH*BB];
__device__ float g_hd  [BB*DHH];         // [b][u] (attention reads)
__device__ float g_hdT [DHH*BB];         // [u][b] (GEMM k-major)
__device__ float g_cdT [DHH*BB];
__device__ float g_ctxP[2*DHH*BB];       // [half][d][b] unnormalized partial ctx
__device__ float g_attM[2*BB];           // [b*2+half] local max
__device__ float g_attS[2*BB];           // [b*2+half] local sum
__device__ float g_Whhp[2*G4H*HH];       // permuted rows [dir][np][k]
__device__ float g_Wihp[2*G4H*EE];
__device__ float g_bep [2*G4H];
__device__ float g_Wcat[GD*1024];        // permuted rows: [Wih_d[:, :512] | Whh_d]
__device__ float g_Wmid0[GD*1024];       // permuted rows: Wih_d[:,512:1536] with h-cols += Wprev
__device__ float g_Wprev[GD*DHH];        // permuted rows: Wih_d[:, 1536:2048]
__device__ float g_bdp [GD];
__device__ float g_ohcp[LMAXX*GD];

// ---------------- flag-tree grid barrier ----------------
__device__ unsigned g_flags[NBD * 32];   // one flag per block, own 128B line
__device__ unsigned g_rel;               // release word (monotonic generation)

__device__ __forceinline__ unsigned bar_base() {
    unsigned v;
    asm volatile("ld.global.u32 %0, [%1];" : "=r"(v) : "l"(&g_rel));
    return v;
}

__device__ __forceinline__ void gsync2(int blk, unsigned gen) {
    __syncthreads();
    if (threadIdx.x == 0)
        asm volatile("st.release.gpu.u32 [%0], %1;" :: "l"(&g_flags[blk * 32]), "r"(gen) : "memory");
    if (blk == 0) {
        if (threadIdx.x < NBD) {
            unsigned v;
            while (true) {
                asm volatile("ld.acquire.gpu.u32 %0, [%1];" : "=r"(v) : "l"(&g_flags[threadIdx.x * 32]) : "memory");
                if ((int)(v - gen) >= 0) break;
                __nanosleep(64);
            }
        }
        __syncthreads();
        if (threadIdx.x == 0)
            asm volatile("st.release.gpu.u32 [%0], %1;" :: "l"(&g_rel), "r"(gen) : "memory");
    } else if (threadIdx.x == 0) {
        unsigned v;
        while (true) {
            asm volatile("ld.acquire.gpu.u32 %0, [%1];" : "=r"(v) : "l"(&g_rel) : "memory");
            if ((int)(v - gen) >= 0) break;
            __nanosleep(64);
        }
    }
    __syncthreads();
}

__device__ __forceinline__ float sigf(float x) { return 1.0f / (1.0f + __expf(-x)); }

// packed f32x2 FMA (SASS FFMA2: 2 MACs/instr)
__device__ __forceinline__ ull fma2(ull a, ull b, ull c) {
    ull d;
    asm("fma.rn.f32x2 %0, %1, %2, %3;" : "=l"(d) : "l"(a), "l"(b), "l"(c));
    return d;
}
__device__ __forceinline__ float2 unpack2(ull v) {
    float2 r;
    asm("mov.b64 {%0, %1}, %2;" : "=f"(r.x), "=f"(r.y) : "l"(v));
    return r;
}

// ---------------- prep ----------------
#define Z_TOTAL 196608
#define PREP_TOTAL (Z_TOTAL + 524288 + 1048576 + 2048 + 2097152 + 2097152 + 1048576 + 2048 + 8192)
__global__ void k_prep(const float* __restrict__ Whh_f, const float* __restrict__ Whh_b,
                       const float* __restrict__ Wih_f, const float* __restrict__ Wih_b,
                       const float* __restrict__ bih_f, const float* __restrict__ bhh_f,
                       const float* __restrict__ bih_b, const float* __restrict__ bhh_b,
                       const float* __restrict__ Wih_d, const float* __restrict__ Whh_d,
                       const float* __restrict__ bih_d, const float* __restrict__ bhh_d) {
    long long i = (long long)blockIdx.x * 256 + threadIdx.x;
    if (i < Z_TOTAL) {
        if (i < 65536) g_hencT[i] = 0.f;
        else if (i < 98304) g_cencT[i - 65536] = 0.f;
        else if (i < 131072) g_hd[i - 98304] = 0.f;
        else if (i < 163840) g_hdT[i - 131072] = 0.f;
        else g_cdT[i - 163840] = 0.f;
        return;
    }
    i -= Z_TOTAL;
    if (i < 524288) { // Whhp
        int dir = (int)(i >> 18), r = (int)(i & 262143);
        int np = r >> 8, k = r & 255;
        int n = enperm(np);
        g_Whhp[i] = (dir ? Whh_b : Whh_f)[n * HH + k];
        return;
    }
    i -= 524288;
    if (i < 1048576) { // Wihp
        int dir = (int)(i >> 19), r = (int)(i & 524287);
        int np = r >> 9, k = r & 511;
        int n = enperm(np);
        g_Wihp[i] = (dir ? Wih_b : Wih_f)[n * EE + k];
        return;
    }
    i -= 1048576;
    if (i < 2048) { // encoder bias
        int dir = (int)(i >> 10), np = (int)(i & 1023);
        int n = enperm(np);
        g_bep[i] = dir ? (bih_b[n] + bhh_b[n]) : (bih_f[n] + bhh_f[n]);
        return;
    }
    i -= 2048;
    if (i < 2097152) { // Wcat
        int np = (int)(i >> 10), k = (int)(i & 1023);
        int n = deperm(np);
        g_Wcat[i] = (k < 512) ? Wih_d[(size_t)n * LDWD + k] : Whh_d[(size_t)n * DHH + (k - 512)];
        return;
    }
    i -= 2097152;
    if (i < 2097152) { // Wmid0 = Wih_d[:,512:1536] with first 512 k-cols += Wprev
        int np = (int)(i >> 10), k = (int)(i & 1023);
        int n = deperm(np);
        float v = Wih_d[(size_t)n * LDWD + 512 + k];
        if (k < 512) v += Wih_d[(size_t)n * LDWD + 1536 + k];
        g_Wmid0[i] = v;
        return;
    }
    i -= 2097152;
    if (i < 1048576) { // Wprev
        int np = (int)(i >> 9), k = (int)(i & 511);
        int n = deperm(np);
        g_Wprev[i] = Wih_d[(size_t)n * LDWD + 1536 + k];
        return;
    }
    i -= 1048576;
    if (i < 2048) { // decoder bias
        int n = deperm((int)i);
        g_bdp[i] = bih_d[n] + bhh_d[n];
        return;
    }
    i -= 2048;
    if (i < 8192) { // one-hot columns
        int lvl = (int)(i >> 11), np = (int)(i & 2047);
        int n = deperm(np);
        g_ohcp[i] = Wih_d[(size_t)n * LDWD + GD + lvl];
        return;
    }
}

__global__ void k_embed(const int* __restrict__ seqs, const float* __restrict__ emb) {
    int m = blockIdx.x;            // m = s*64 + b
    int s0 = m >> 6, b = m & 63;
    int row = seqs[b * SS + s0];
    const float4* src = (const float4*)(emb + (size_t)row * EE);
    float4* dst = (float4*)(g_x + (size_t)m * EE);
    dst[threadIdx.x] = src[threadIdx.x];
}

// ---------------- precompute GEMM core (64x64 tiles, ~31 TF/s measured) ----------------
__device__ __forceinline__ void gemm_core(const float* __restrict__ A, int lda,
                        const float* __restrict__ A2, const float* __restrict__ Asub,
                        const float* __restrict__ W, int ldw,
                        float* __restrict__ C, int N, int K,
                        const float* __restrict__ add, const float* __restrict__ bias,
                        int tpose, int m0, int n0) {
    __shared__ __align__(16) float As[16][68];
    __shared__ __align__(16) float Ws[16][68];
    int tid = threadIdx.x;
    int tm = (tid >> 4) << 2, tn = (tid & 15) << 2;
    float acc[4][4] = {};
    for (int k0 = 0; k0 < K; k0 += 16) {
        const float* Asrc = A;
        int kk0 = k0;
        bool second = (A2 && k0 >= 512);
        if (second) { Asrc = A2; kk0 = k0 - 512; }
        #pragma unroll
        for (int i = tid; i < 1024; i += 256) {
            int r = i >> 4, k = i & 15;
            float v = Asrc[(size_t)(m0 + r) * lda + kk0 + k];
            if (Asub && !second) v -= Asub[(size_t)(m0 + r) * lda + kk0 + k];
            As[k][r] = v;
            Ws[k][r] = W[(size_t)(n0 + r) * ldw + k0 + k];
        }
        __syncthreads();
        #pragma unroll
        for (int k = 0; k < 16; k++) {
            float4 a4 = *(const float4*)&As[k][tm];
            float4 w4 = *(const float4*)&Ws[k][tn];
            acc[0][0] += a4.x * w4.x; acc[0][1] += a4.x * w4.y; acc[0][2] += a4.x * w4.z; acc[0][3] += a4.x * w4.w;
            acc[1][0] += a4.y * w4.x; acc[1][1] += a4.y * w4.y; acc[1][2] += a4.y * w4.z; acc[1][3] += a4.y * w4.w;
            acc[2][0] += a4.z * w4.x; acc[2][1] += a4.z * w4.y; acc[2][2] += a4.z * w4.z; acc[2][3] += a4.z * w4.w;
            acc[3][0] += a4.w * w4.x; acc[3][1] += a4.w * w4.y; acc[3][2] += a4.w * w4.z; acc[3][3] += a4.w * w4.w;
        }
        __syncthreads();
    }
    #pragma unroll
    for (int i = 0; i < 4; i++)
        #pragma unroll
        for (int j = 0; j < 4; j++) {
            int m = m0 + tm + i, n = n0 + tn + j;
            float v = acc[i][j];
            if (bias) v += bias[n];
            if (tpose) {
                size_t idx = ((size_t)(m >> 6) * N + n) * 64 + (m & 63);
                if (add) v += add[idx];
                C[idx] = v;
            } else {
                size_t idx = (size_t)m * N + n;
                if (add) v += add[idx];
                C[idx] = v;
            }
        }
}

__global__ void __launch_bounds__(256) k_encg() {
    int z = blockIdx.z;
    gemm_core(g_x, EE, nullptr, nullptr,
              g_Wihp + (size_t)z * G4H * EE, EE,
              z ? g_gxb : g_gxf, G4H, EE,
              nullptr, g_bep + z * G4H, 1,
              blockIdx.x * 64, blockIdx.y * 64);
}

__global__ void __launch_bounds__(256) k_pre(const float* __restrict__ Wl) {
    if (blockIdx.y < 32) {
        gemm_core(g_h, DHH, g_x, nullptr, g_Wmid0, 1024, g_pre0, GD, 1024,
                  nullptr, g_bdp, 1, blockIdx.x * 64, blockIdx.y * 64);
    } else {
        gemm_core(g_h, DHH, nullptr, nullptr, Wl, DHH, g_wh, DHH, DHH,
                  nullptr, nullptr, 0, blockIdx.x * 64, (blockIdx.y - 32) * 64);
    }
}

__global__ void __launch_bounds__(256) k_pre1() {
    gemm_core(g_dout, DHH, nullptr, g_h, g_Wprev, DHH, g_pre1, GD, DHH,
              g_pre0, nullptr, 1, blockIdx.x * 64, blockIdx.y * 64);
}

// ---------------- W-resident f32x2 GEMM half (512 threads, k-split) ----------------
// AT: [K][64] k-major; wp0 = Wsm + kbase*32 + 4*np (splatted pairs); Asm staging [64][64].
// Thread map: np=(lane>>2), bp=w8*4+(lane&3) (w8 = (tid&255)>>5), khalf=tid>>8.
// Staging: kl=tid>>3 (0..63), b8=(tid&7)*8 (2 float4 per thread).
template<int CHUNKS>
__device__ __forceinline__ void wres2(const float* __restrict__ AT,
                                      const float* __restrict__ wp0,
                                      float (*Asm)[64],
                                      int bp, int kl, int b8, int khalf,
                                      ull& acc0, ull& acc1) {
    float4 pf0 = *(const float4*)&AT[kl * 64 + b8];
    float4 pf1 = *(const float4*)&AT[kl * 64 + b8 + 4];
    for (int c = 0; c < CHUNKS; c++) {
        __syncthreads();
        *(float4*)&Asm[kl][b8]     = pf0;
        *(float4*)&Asm[kl][b8 + 4] = pf1;
        __syncthreads();
        if (c < CHUNKS - 1) {
            const float* src = AT + (c + 1) * 4096;
            pf0 = *(const float4*)&src[kl * 64 + b8];
            pf1 = *(const float4*)&src[kl * 64 + b8 + 4];
        }
        const float* wp = wp0 + (c * 64 + khalf * 32) * 32;
        #pragma unroll
        for (int kk = 0; kk < 32; kk++) {
            ull a = *(const ull*)&Asm[khalf * 32 + kk][2 * bp];
            ulonglong2 wv = *(const ulonglong2*)(wp + kk * 32);
            acc0 = fma2(a, wv.x, acc0);
            acc1 = fma2(a, wv.y, acc1);
        }
    }
}

// merged-fill variant: A element = P0*c0 + P1*c1 (flash-softmax ctx merge)
template<int CHUNKS>
__device__ __forceinline__ void wres2m(const float* __restrict__ P0,
                                       const float* __restrict__ P1,
                                       float4 c0a, float4 c1a, float4 c0b, float4 c1b,
                                       const float* __restrict__ wp0,
                                       float (*Asm)[64],
                                       int bp, int kl, int b8, int khalf,
                                       ull& acc0, ull& acc1) {
    #define MLD(off, c0, c1) ({ float4 x0 = *(const float4*)&P0[off]; \
                        float4 x1 = *(const float4*)&P1[off]; \
                        float4 r; \
                        r.x = x0.x * c0.x + x1.x * c1.x; \
                        r.y = x0.y * c0.y + x1.y * c1.y; \
                        r.z = x0.z * c0.z + x1.z * c1.z; \
                        r.w = x0.w * c0.w + x1.w * c1.w; r; })
    float4 pf0 = MLD(kl * 64 + b8, c0a, c1a);
    float4 pf1 = MLD(kl * 64 + b8 + 4, c0b, c1b);
    for (int c = 0; c < CHUNKS; c++) {
        __syncthreads();
        *(float4*)&Asm[kl][b8]     = pf0;
        *(float4*)&Asm[kl][b8 + 4] = pf1;
        __syncthreads();
        if (c < CHUNKS - 1) {
            int base = (c + 1) * 4096;
            pf0 = MLD(base + kl * 64 + b8, c0a, c1a);
            pf1 = MLD(base + kl * 64 + b8 + 4, c0b, c1b);
        }
        const float* wp = wp0 + (c * 64 + khalf * 32) * 32;
        #pragma unroll
        for (int kk = 0; kk < 32; kk++) {
            ull a = *(const ull*)&Asm[khalf * 32 + kk][2 * bp];
            ulonglong2 wv = *(const ulonglong2*)(wp + kk * 32);
            acc0 = fma2(a, wv.x, acc0);
            acc1 = fma2(a, wv.y, acc1);
        }
    }
    #undef MLD
}

// ---------------- persistent encoder (512 threads) ----------------
#define SMEM_ENC ((HH * 32 + 64 * 64) * 4)   // 48KB: splatted Wsm + Asm
__global__ void __launch_bounds__(TPB, 1) enc_persist() {
    extern __shared__ __align__(16) float dyn[];
    float* Wsm = dyn;                          // [256*32] splatted
    float (*Asm)[64] = (float(*)[64])(dyn + HH * 32);
    ull* cmb = (ull*)Asm;                      // reuse staging for k-half combine
    __shared__ float gsm[16][64];
    int blk = blockIdx.x, tid = threadIdx.x;
    int dir = blk >> 6, ub = blk & 63;
    for (int i = tid; i < 16 * HH; i += TPB) {
        int r = i >> 8, k = i & 255;
        float v = g_Whhp[((size_t)dir * G4H + ub * 16 + r) * HH + k];
        int base = k * 32 + (r >> 1) * 4 + (r & 1) * 2;
        Wsm[base] = v; Wsm[base + 1] = v;
    }
    __syncthreads();
    int lane = tid & 31;
    int w8 = (tid & 255) >> 5;
    int np = lane >> 2, bp = w8 * 4 + (lane & 3);
    int khalf = tid >> 8;
    int kl = tid >> 3, b8 = (tid & 7) << 3;
    int uu = tid >> 6, bc = tid & 63;          // cell (tid<256)
    const float* wp0 = Wsm + 4 * np;
    unsigned gen = bar_base();
    int p = 0;
    for (int t = 0; t < SS; t++) {
        const float* AT = g_hencT + ((size_t)p * 2 + dir) * HH * BB;
        ull acc0 = 0ull, acc1 = 0ull;
        wres2<4>(AT, wp0, Asm, bp, kl, b8, khalf, acc0, acc1);
        int s0 = dir ? (SS - 1 - t) : t;
        // combine k-halves
        __syncthreads();
        cmb[tid * 2] = acc0; cmb[tid * 2 + 1] = acc1;
        __syncthreads();
        if (tid < 256) {
            float2 a0 = unpack2(acc0), a1 = unpack2(acc1);
            float2 o0 = unpack2(cmb[(tid + 256) * 2]), o1 = unpack2(cmb[(tid + 256) * 2 + 1]);
            a0.x += o0.x; a0.y += o0.y; a1.x += o1.x; a1.y += o1.y;
            const float* gx = (dir ? g_gxb : g_gxf) + ((size_t)s0 * G4H + ub * 16) * 64;
            float2 g0 = *(const float2*)&gx[(2 * np) * 64 + 2 * bp];
            float2 g1 = *(const float2*)&gx[(2 * np + 1) * 64 + 2 * bp];
            *(float2*)&gsm[2 * np][2 * bp]     = make_float2(a0.x + g0.x, a0.y + g0.y);
            *(float2*)&gsm[2 * np + 1][2 * bp] = make_float2(a1.x + g1.x, a1.y + g1.y);
        }
        __syncthreads();
        if (tid < 256) {
            float gi = gsm[uu][bc], gf = gsm[4 + uu][bc], gg = gsm[8 + uu][bc], go = gsm[12 + uu][bc];
            int u = ub * 4 + uu;
            size_t ci = ((size_t)dir * HH + u) * BB + bc;
            float c = g_cencT[ci];
            c = sigf(gf) * c + sigf(gi) * tanhf(gg);
            float hn = sigf(go) * tanhf(c);
            g_cencT[ci] = c;
            g_hencT[((size_t)(p ^ 1) * 2 + dir) * HH * BB + (size_t)u * BB + bc] = hn;
            g_h[((size_t)s0 * BB + bc) * DHH + dir * HH + u] = hn;
        }
        p ^= 1;
        gsync2(blk, ++gen);
    }
}

// ---------------- persistent decoder (512 threads) ----------------
#define SMEM_DEC ((1024 * 32 + 64 * 64) * 4)   // 144KB: splatted Wsm + Asm
__global__ void __launch_bounds__(TPB, 1) dec_persist(int l0, int l1) {
    extern __shared__ __align__(16) float dyn[];
    float* Wsm = dyn;                           // [1024*32] splatted
    float (*Asm)[64] = (float(*)[64])(dyn + 1024 * 32);
    ull* cmb = (ull*)Asm;                       // reuse staging for k-half combine
    __shared__ float gsm[16][64];
    __shared__ __align__(16) float hd_s[DHH];
    __shared__ float sc[64];
    __shared__ float red[64];
    __shared__ __align__(16) float c0sm[64], c1sm[64];
    int blk = blockIdx.x, tid = threadIdx.x;
    int half = blk & 1, ab = blk >> 1;          // attention: 2 blocks per batch
    for (int i = tid; i < 16 * 1024; i += TPB) {
        int r = i >> 10, k = i & 1023;
        float v = g_Wcat[((size_t)blk * 16 + r) * 1024 + k];
        int base = k * 32 + (r >> 1) * 4 + (r & 1) * 2;
        Wsm[base] = v; Wsm[base + 1] = v;
    }
    __syncthreads();
    int lane = tid & 31;
    int w16 = tid >> 5;                         // 0..15
    int w8 = (tid & 255) >> 5;
    int np = lane >> 2, bp = w8 * 4 + (lane & 3);
    int khalf = tid >> 8;
    int kl = tid >> 3, b8 = (tid & 7) << 3;
    int uu = tid >> 6, bc = tid & 63;           // cell (tid<256)
    const float* wpA = Wsm + 512 * 32 + 4 * np;   // hd half (k 512..1023)
    const float* wpB = Wsm + 4 * np;              // ctx half (k 0..511)
    unsigned gen = bar_base();
    for (int lvl = l0; lvl < l1; lvl++) {
        const float* pre = (lvl == 0) ? g_pre0 : g_pre1;
        float oh0 = g_ohcp[lvl * GD + blk * 16 + 2 * np];
        float oh1 = g_ohcp[lvl * GD + blk * 16 + 2 * np + 1];
        for (int t = 0; t < SS; t++) {
            // ===== phase A: attention half first (L2-bound), then hd-half GEMM =====
            {
                for (int i = tid; i < DHH; i += TPB) hd_s[i] = g_hd[ab * DHH + i];
                __syncthreads();
                for (int it = 0; it < 4; it++) {
                    int s_loc = w16 * 4 + it;
                    int s = half * 64 + s_loc;
                    const float4* w4 = (const float4*)(g_wh + ((size_t)s * BB + ab) * DHH);
                    const float4* h4 = (const float4*)hd_s;
                    float sum = 0.f;
                    #pragma unroll
                    for (int qq = 0; qq < 4; qq++) {
                        float4 a = w4[lane * 4 + qq];
                        float4 c = h4[lane * 4 + qq];
                        sum += a.x * c.x + a.y * c.y + a.z * c.z + a.w * c.w;
                    }
                    #pragma unroll
                    for (int off = 16; off; off >>= 1) sum += __shfl_xor_sync(0xffffffffu, sum, off);
                    if (lane == 0) sc[s_loc] = sum;
                }
                __syncthreads();
                if (tid < 64) red[tid] = sc[tid];
                __syncthreads();
                for (int off = 32; off; off >>= 1) {
                    if (tid < off) red[tid] = fmaxf(red[tid], red[tid + off]);
                    __syncthreads();
                }
                float mx = red[0];
                __syncthreads();
                if (tid < 64) { float e = __expf(sc[tid] - mx); sc[tid] = e; red[tid] = e; }
                __syncthreads();
                for (int off = 32; off; off >>= 1) {
                    if (tid < off) red[tid] += red[tid + off];
                    __syncthreads();
                }
                if (tid == 0) { g_attM[ab * 2 + half] = mx; g_attS[ab * 2 + half] = red[0]; }
                // partial unnormalized ctx over this half's 64 s (1 d per thread)
                {
                    int d = tid;
                    float acc = 0.f;
                    #pragma unroll 8
                    for (int s_loc = 0; s_loc < 64; s_loc++)
                        acc += sc[s_loc] * g_h[(((size_t)(half * 64 + s_loc)) * BB + ab) * DHH + d];
                    g_ctxP[((size_t)half * DHH + d) * 64 + ab] = acc;
                }
                __syncthreads();
            }
            ull acc0 = 0ull, acc1 = 0ull;
            wres2<8>(g_hdT, wpA, Asm, bp, kl, b8, khalf, acc0, acc1);
            gsync2(blk, ++gen);
            // ===== phase B: flash-merge + ctx-half GEMM + combine + cell =====
            if (tid < 64) {
                float m0 = g_attM[tid * 2], m1 = g_attM[tid * 2 + 1];
                float M = fmaxf(m0, m1);
                float e0 = __expf(m0 - M), e1 = __expf(m1 - M);
                float den = g_attS[tid * 2] * e0 + g_attS[tid * 2 + 1] * e1;
                c0sm[tid] = e0 / den;
                c1sm[tid] = e1 / den;
            }
            __syncthreads();
            float4 c0a = *(const float4*)&c0sm[b8];
            float4 c0b = *(const float4*)&c0sm[b8 + 4];
            float4 c1a = *(const float4*)&c1sm[b8];
            float4 c1b = *(const float4*)&c1sm[b8 + 4];
            wres2m<8>(g_ctxP, g_ctxP + DHH * 64, c0a, c1a, c0b, c1b,
                      wpB, Asm, bp, kl, b8, khalf, acc0, acc1);
            // combine k-halves
            __syncthreads();
            cmb[tid * 2] = acc0; cmb[tid * 2 + 1] = acc1;
            __syncthreads();
            if (tid < 256) {
                float2 a0 = unpack2(acc0), a1 = unpack2(acc1);
                float2 o0 = unpack2(cmb[(tid + 256) * 2]), o1 = unpack2(cmb[(tid + 256) * 2 + 1]);
                a0.x += o0.x; a0.y += o0.y; a1.x += o1.x; a1.y += o1.y;
                const float* pr = pre + ((size_t)t * GD + blk * 16) * 64;
                float2 p0 = *(const float2*)&pr[(2 * np) * 64 + 2 * bp];
                float2 p1 = *(const float2*)&pr[(2 * np + 1) * 64 + 2 * bp];
                *(float2*)&gsm[2 * np][2 * bp]     = make_float2(a0.x + p0.x + oh0, a0.y + p0.y + oh0);
                *(float2*)&gsm[2 * np + 1][2 * bp] = make_float2(a1.x + p1.x + oh1, a1.y + p1.y + oh1);
            }
            __syncthreads();
            if (tid < 256) {
                float gi = gsm[uu][bc], gf = gsm[4 + uu][bc], gg = gsm[8 + uu][bc], go = gsm[12 + uu][bc];
                int u = blk * 4 + uu;
                size_t ci = (size_t)u * BB + bc;
                float c = g_cdT[ci];
                c = sigf(gf) * c + sigf(gi) * tanhf(gg);
                float hn = sigf(go) * tanhf(c);
                g_cdT[ci] = c;
                g_hdT[ci] = hn;
                g_hd[(size_t)bc * DHH + u] = hn;
                g_dout[(((size_t)lvl * SS + t) * BB + bc) * DHH + u] = hn;
            }
            gsync2(blk, ++gen);
        }
    }
}

// ---------------- output projection ----------------
__global__ void out_proj(const float* __restrict__ W2, const float* __restrict__ b2,
                         float* __restrict__ out) {
    int m = blockIdx.x;
    int lane = threadIdx.x;
    const float* drow = g_dout + (size_t)m * DHH;
    float acc[CC] = {};
    for (int k = lane; k < DHH; k += 32) {
        float d = drow[k];
        #pragma unroll
        for (int c = 0; c < CC; c++) acc[c] += d * W2[c * DHH + k];
    }
    #pragma unroll
    for (int c = 0; c < CC; c++) {
        float v = acc[c];
        #pragma unroll
        for (int off = 16; off; off >>= 1) v += __shfl_xor_sync(0xffffffffu, v, off);
        if (lane == 0) out[(size_t)m * CC + c] = v + b2[c];
    }
}

// ---------------- host ----------------
extern "C" void kernel_launch(void* const* d_in, const int* in_sizes, int n_in,
                              void* d_out, int out_size) {
    const int*   seqs  = (const int*)d_in[0];
    const float* emb   = (const float*)d_in[2];
    const float* Wih_f = (const float*)d_in[3];
    const float* Whh_f = (const float*)d_in[4];
    const float* bih_f = (const float*)d_in[5];
    const float* bhh_f = (const float*)d_in[6];
    const float* Wih_b = (const float*)d_in[7];
    const float* Whh_b = (const float*)d_in[8];
    const float* bih_b = (const float*)d_in[9];
    const float* bhh_b = (const float*)d_in[10];
    const float* Wl    = (const float*)d_in[11];
    const float* Wih_d = (const float*)d_in[12];
    const float* Whh_d = (const float*)d_in[13];
    const float* bih_d = (const float*)d_in[14];
    const float* bhh_d = (const float*)d_in[15];
    const float* W2    = (const float*)d_in[16];
    const float* b2    = (const float*)d_in[17];
    float* out = (float*)d_out;

    cudaFuncSetAttribute(enc_persist, cudaFuncAttributeMaxDynamicSharedMemorySize, SMEM_ENC);
    cudaFuncSetAttribute(dec_persist, cudaFuncAttributeMaxDynamicSharedMemorySize, SMEM_DEC);

    // 0: prep
    k_prep<<<(PREP_TOTAL + 255) / 256, 256>>>(Whh_f, Whh_b, Wih_f, Wih_b,
                                              bih_f, bhh_f, bih_b, bhh_b,
                                              Wih_d, Whh_d, bih_d, bhh_d);
    // 1: embed
    k_embed<<<SS * BB, 128>>>(seqs, emb);
    // 2: encoder input GEMMs (both dirs, transposed out)
    k_encg<<<dim3(SS * BB / 64, G4H / 64, 2), 256>>>();
    // 3: encoder recurrence (512 threads)
    enc_persist<<<NBE, TPB, SMEM_ENC>>>();
    // 4: pre0 (+bias, transposed) and wh, one launch
    k_pre<<<dim3(SS * BB / 64, 40), 256>>>(Wl);
    // 5: decoder level 0 (512 threads)
    dec_persist<<<NBD, TPB, SMEM_DEC>>>(0, 1);
    // 6: pre1 = pre0 + (dout0 - h)@Wprev
    k_pre1<<<dim3(SS * BB / 64, GD / 64), 256>>>();
    // 7: decoder levels 1-3
    dec_persist<<<NBD, TPB, SMEM_DEC>>>(1, 4);
    // 8: logits
    out_proj<<<LMAXX * SS * BB, 32>>>(W2, b2, out);
}

// round 14
// speedup vs baseline: 1.0081x; 1.0081x over previous
#include <cuda_runtime.h>
#include <math.h>

// ---------------- problem dims ----------------
#define SS    128
#define BB    64
#define EE    512
#define HH    256
#define DHH   512
#define G4H   1024
#define GD    2048
#define LDWD  2052
#define LMAXX 4
#define CC    9

#define NBE   128
#define NBD   128
#define TPB   512

typedef unsigned long long ull;

// gate-locality permutations: block owns all 4 gates of 4 units
__device__ __forceinline__ int enperm(int np) { return (((np >> 2) & 3) << 8) + ((np >> 4) << 2) + (np & 3); }
__device__ __forceinline__ int deperm(int np) { return (((np >> 2) & 3) << 9) + ((np >> 4) << 2) + (np & 3); }

// ---------------- static device scratch ----------------
__device__ float g_x   [SS*BB*EE];
__device__ float g_gxf [SS*BB*G4H];      // TRANSPOSED: [s][np][b]
__device__ float g_gxb [SS*BB*G4H];      // TRANSPOSED: [s][np][b]
__device__ float g_h   [SS*BB*DHH];      // [s][b][d] row-major
__device__ float g_wh  [SS*BB*DHH];      // [s][b][d] row-major
__device__ float g_pre0[SS*BB*GD];       // TRANSPOSED: [t][np][b]
__device__ float g_pre1[SS*BB*GD];       // TRANSPOSED: [t][np][b]
__device__ float g_dout[LMAXX*SS*BB*DHH];// [lvl][t][b][u]
__device__ float g_hencT[2*2*HH*BB];     // [p][dir][u][b]
__device__ float g_cencT[2*HH*BB];
__device__ float g_hd  [BB*DHH];         // [b][u] (attention reads)
__device__ float g_hdT [DHH*BB];         // [u][b] (GEMM k-major)
__device__ float g_cdT [DHH*BB];
__device__ float g_ctxP[2*DHH*BB];       // [half][d][b] unnormalized partial ctx
__device__ float g_attM[2*BB];           // [b*2+half] local max
__device__ float g_attS[2*BB];           // [b*2+half] local sum
__device__ float g_Whhp[2*G4H*HH];       // permuted rows [dir][np][k]
__device__ float g_Wihp[2*G4H*EE];
__device__ float g_bep [2*G4H];
__device__ float g_Wcat[GD*1024];        // permuted rows: [Wih_d[:, :512] | Whh_d]
__device__ float g_Wmid0[GD*1024];       // permuted rows: Wih_d[:,512:1536] with h-cols += Wprev
__device__ float g_Wprev[GD*DHH];        // permuted rows: Wih_d[:, 1536:2048]
__device__ float g_bdp [GD];
__device__ float g_ohcp[LMAXX*GD];

// ---------------- flag-tree grid barrier ----------------
__device__ unsigned g_flags[NBD * 32];   // one flag per block, own 128B line
__device__ unsigned g_rel;               // release word (monotonic generation)

__device__ __forceinline__ unsigned bar_base() {
    unsigned v;
    asm volatile("ld.global.u32 %0, [%1];" : "=r"(v) : "l"(&g_rel));
    return v;
}

__device__ __forceinline__ void gsync2(int blk, unsigned gen) {
    __syncthreads();
    if (threadIdx.x == 0)
        asm volatile("st.release.gpu.u32 [%0], %1;" :: "l"(&g_flags[blk * 32]), "r"(gen) : "memory");
    if (blk == 0) {
        if (threadIdx.x < NBD) {
            unsigned v;
            while (true) {
                asm volatile("ld.acquire.gpu.u32 %0, [%1];" : "=r"(v) : "l"(&g_flags[threadIdx.x * 32]) : "memory");
                if ((int)(v - gen) >= 0) break;
                __nanosleep(64);
            }
        }
        __syncthreads();
        if (threadIdx.x == 0)
            asm volatile("st.release.gpu.u32 [%0], %1;" :: "l"(&g_rel), "r"(gen) : "memory");
    } else if (threadIdx.x == 0) {
        unsigned v;
        while (true) {
            asm volatile("ld.acquire.gpu.u32 %0, [%1];" : "=r"(v) : "l"(&g_rel) : "memory");
            if ((int)(v - gen) >= 0) break;
            __nanosleep(64);
        }
    }
    __syncthreads();
}

__device__ __forceinline__ float sigf(float x) { return 1.0f / (1.0f + __expf(-x)); }

// packed f32x2 FMA (SASS FFMA2: 2 MACs/instr)
__device__ __forceinline__ ull fma2(ull a, ull b, ull c) {
    ull d;
    asm("fma.rn.f32x2 %0, %1, %2, %3;" : "=l"(d) : "l"(a), "l"(b), "l"(c));
    return d;
}
__device__ __forceinline__ float2 unpack2(ull v) {
    float2 r;
    asm("mov.b64 {%0, %1}, %2;" : "=f"(r.x), "=f"(r.y) : "l"(v));
    return r;
}

// ---------------- prep ----------------
#define Z_TOTAL 196608
#define PREP_TOTAL (Z_TOTAL + 524288 + 1048576 + 2048 + 2097152 + 2097152 + 1048576 + 2048 + 8192)
__global__ void k_prep(const float* __restrict__ Whh_f, const float* __restrict__ Whh_b,
                       const float* __restrict__ Wih_f, const float* __restrict__ Wih_b,
                       const float* __restrict__ bih_f, const float* __restrict__ bhh_f,
                       const float* __restrict__ bih_b, const float* __restrict__ bhh_b,
                       const float* __restrict__ Wih_d, const float* __restrict__ Whh_d,
                       const float* __restrict__ bih_d, const float* __restrict__ bhh_d) {
    long long i = (long long)blockIdx.x * 256 + threadIdx.x;
    if (i < Z_TOTAL) {
        if (i < 65536) g_hencT[i] = 0.f;
        else if (i < 98304) g_cencT[i - 65536] = 0.f;
        else if (i < 131072) g_hd[i - 98304] = 0.f;
        else if (i < 163840) g_hdT[i - 131072] = 0.f;
        else g_cdT[i - 163840] = 0.f;
        return;
    }
    i -= Z_TOTAL;
    if (i < 524288) { // Whhp
        int dir = (int)(i >> 18), r = (int)(i & 262143);
        int np = r >> 8, k = r & 255;
        int n = enperm(np);
        g_Whhp[i] = (dir ? Whh_b : Whh_f)[n * HH + k];
        return;
    }
    i -= 524288;
    if (i < 1048576) { // Wihp
        int dir = (int)(i >> 19), r = (int)(i & 524287);
        int np = r >> 9, k = r & 511;
        int n = enperm(np);
        g_Wihp[i] = (dir ? Wih_b : Wih_f)[n * EE + k];
        return;
    }
    i -= 1048576;
    if (i < 2048) { // encoder bias
        int dir = (int)(i >> 10), np = (int)(i & 1023);
        int n = enperm(np);
        g_bep[i] = dir ? (bih_b[n] + bhh_b[n]) : (bih_f[n] + bhh_f[n]);
        return;
    }
    i -= 2048;
    if (i < 2097152) { // Wcat
        int np = (int)(i >> 10), k = (int)(i & 1023);
        int n = deperm(np);
        g_Wcat[i] = (k < 512) ? Wih_d[(size_t)n * LDWD + k] : Whh_d[(size_t)n * DHH + (k - 512)];
        return;
    }
    i -= 2097152;
    if (i < 2097152) { // Wmid0 = Wih_d[:,512:1536] with first 512 k-cols += Wprev
        int np = (int)(i >> 10), k = (int)(i & 1023);
        int n = deperm(np);
        float v = Wih_d[(size_t)n * LDWD + 512 + k];
        if (k < 512) v += Wih_d[(size_t)n * LDWD + 1536 + k];
        g_Wmid0[i] = v;
        return;
    }
    i -= 2097152;
    if (i < 1048576) { // Wprev
        int np = (int)(i >> 9), k = (int)(i & 511);
        int n = deperm(np);
        g_Wprev[i] = Wih_d[(size_t)n * LDWD + 1536 + k];
        return;
    }
    i -= 1048576;
    if (i < 2048) { // decoder bias
        int n = deperm((int)i);
        g_bdp[i] = bih_d[n] + bhh_d[n];
        return;
    }
    i -= 2048;
    if (i < 8192) { // one-hot columns
        int lvl = (int)(i >> 11), np = (int)(i & 2047);
        int n = deperm(np);
        g_ohcp[i] = Wih_d[(size_t)n * LDWD + GD + lvl];
        return;
    }
}

__global__ void k_embed(const int* __restrict__ seqs, const float* __restrict__ emb) {
    int m = blockIdx.x;            // m = s*64 + b
    int s0 = m >> 6, b = m & 63;
    int row = seqs[b * SS + s0];
    const float4* src = (const float4*)(emb + (size_t)row * EE);
    float4* dst = (float4*)(g_x + (size_t)m * EE);
    dst[threadIdx.x] = src[threadIdx.x];
}

// ---------------- precompute GEMM core (64x64 tiles, ~31 TF/s measured) ----------------
__device__ __forceinline__ void gemm_core(const float* __restrict__ A, int lda,
                        const float* __restrict__ A2, const float* __restrict__ Asub,
                        const float* __restrict__ W, int ldw,
                        float* __restrict__ C, int N, int K,
                        const float* __restrict__ add, const float* __restrict__ bias,
                        int tpose, int m0, int n0) {
    __shared__ __align__(16) float As[16][68];
    __shared__ __align__(16) float Ws[16][68];
    int tid = threadIdx.x;
    int tm = (tid >> 4) << 2, tn = (tid & 15) << 2;
    float acc[4][4] = {};
    for (int k0 = 0; k0 < K; k0 += 16) {
        const float* Asrc = A;
        int kk0 = k0;
        bool second = (A2 && k0 >= 512);
        if (second) { Asrc = A2; kk0 = k0 - 512; }
        #pragma unroll
        for (int i = tid; i < 1024; i += 256) {
            int r = i >> 4, k = i & 15;
            float v = Asrc[(size_t)(m0 + r) * lda + kk0 + k];
            if (Asub && !second) v -= Asub[(size_t)(m0 + r) * lda + kk0 + k];
            As[k][r] = v;
            Ws[k][r] = W[(size_t)(n0 + r) * ldw + k0 + k];
        }
        __syncthreads();
        #pragma unroll
        for (int k = 0; k < 16; k++) {
            float4 a4 = *(const float4*)&As[k][tm];
            float4 w4 = *(const float4*)&Ws[k][tn];
            acc[0][0] += a4.x * w4.x; acc[0][1] += a4.x * w4.y; acc[0][2] += a4.x * w4.z; acc[0][3] += a4.x * w4.w;
            acc[1][0] += a4.y * w4.x; acc[1][1] += a4.y * w4.y; acc[1][2] += a4.y * w4.z; acc[1][3] += a4.y * w4.w;
            acc[2][0] += a4.z * w4.x; acc[2][1] += a4.z * w4.y; acc[2][2] += a4.z * w4.z; acc[2][3] += a4.z * w4.w;
            acc[3][0] += a4.w * w4.x; acc[3][1] += a4.w * w4.y; acc[3][2] += a4.w * w4.z; acc[3][3] += a4.w * w4.w;
        }
        __syncthreads();
    }
    #pragma unroll
    for (int i = 0; i < 4; i++)
        #pragma unroll
        for (int j = 0; j < 4; j++) {
            int m = m0 + tm + i, n = n0 + tn + j;
            float v = acc[i][j];
            if (bias) v += bias[n];
            if (tpose) {
                size_t idx = ((size_t)(m >> 6) * N + n) * 64 + (m & 63);
                if (add) v += add[idx];
                C[idx] = v;
            } else {
                size_t idx = (size_t)m * N + n;
                if (add) v += add[idx];
                C[idx] = v;
            }
        }
}

__global__ void __launch_bounds__(256) k_encg() {
    int z = blockIdx.z;
    gemm_core(g_x, EE, nullptr, nullptr,
              g_Wihp + (size_t)z * G4H * EE, EE,
              z ? g_gxb : g_gxf, G4H, EE,
              nullptr, g_bep + z * G4H, 1,
              blockIdx.x * 64, blockIdx.y * 64);
}

__global__ void __launch_bounds__(256) k_pre(const float* __restrict__ Wl) {
    if (blockIdx.y < 32) {
        gemm_core(g_h, DHH, g_x, nullptr, g_Wmid0, 1024, g_pre0, GD, 1024,
                  nullptr, g_bdp, 1, blockIdx.x * 64, blockIdx.y * 64);
    } else {
        gemm_core(g_h, DHH, nullptr, nullptr, Wl, DHH, g_wh, DHH, DHH,
                  nullptr, nullptr, 0, blockIdx.x * 64, (blockIdx.y - 32) * 64);
    }
}

__global__ void __launch_bounds__(256) k_pre1() {
    gemm_core(g_dout, DHH, nullptr, g_h, g_Wprev, DHH, g_pre1, GD, DHH,
              g_pre0, nullptr, 1, blockIdx.x * 64, blockIdx.y * 64);
}

// ---------------- W-resident f32x2 GEMM half (512 threads, k-split) ----------------
// AT: [K][64] k-major; wp0 = Wsm + kbase*32 + 4*np (splatted pairs); Asm staging [64][64].
// Thread map: np=(lane>>2), bp=w8*4+(lane&3) (w8 = (tid&255)>>5), khalf=tid>>8.
// Staging: kl=tid>>3 (0..63), b8=(tid&7)*8 (2 float4 per thread).
template<int CHUNKS>
__device__ __forceinline__ void wres2(const float* __restrict__ AT,
                                      const float* __restrict__ wp0,
                                      float (*Asm)[64],
                                      int bp, int kl, int b8, int khalf,
                                      ull& acc0, ull& acc1) {
    float4 pf0 = *(const float4*)&AT[kl * 64 + b8];
    float4 pf1 = *(const float4*)&AT[kl * 64 + b8 + 4];
    for (int c = 0; c < CHUNKS; c++) {
        __syncthreads();
        *(float4*)&Asm[kl][b8]     = pf0;
        *(float4*)&Asm[kl][b8 + 4] = pf1;
        __syncthreads();
        if (c < CHUNKS - 1) {
            const float* src = AT + (c + 1) * 4096;
            pf0 = *(const float4*)&src[kl * 64 + b8];
            pf1 = *(const float4*)&src[kl * 64 + b8 + 4];
        }
        const float* wp = wp0 + (c * 64 + khalf * 32) * 32;
        #pragma unroll
        for (int kk = 0; kk < 32; kk++) {
            ull a = *(const ull*)&Asm[khalf * 32 + kk][2 * bp];
            ulonglong2 wv = *(const ulonglong2*)(wp + kk * 32);
            acc0 = fma2(a, wv.x, acc0);
            acc1 = fma2(a, wv.y, acc1);
        }
    }
}

// merged-fill variant: A element = P0*c0 + P1*c1 (flash-softmax ctx merge)
template<int CHUNKS>
__device__ __forceinline__ void wres2m(const float* __restrict__ P0,
                                       const float* __restrict__ P1,
                                       float4 c0a, float4 c1a, float4 c0b, float4 c1b,
                                       const float* __restrict__ wp0,
                                       float (*Asm)[64],
                                       int bp, int kl, int b8, int khalf,
                                       ull& acc0, ull& acc1) {
    #define MLD(off, c0, c1) ({ float4 x0 = *(const float4*)&P0[off]; \
                        float4 x1 = *(const float4*)&P1[off]; \
                        float4 r; \
                        r.x = x0.x * c0.x + x1.x * c1.x; \
                        r.y = x0.y * c0.y + x1.y * c1.y; \
                        r.z = x0.z * c0.z + x1.z * c1.z; \
                        r.w = x0.w * c0.w + x1.w * c1.w; r; })
    float4 pf0 = MLD(kl * 64 + b8, c0a, c1a);
    float4 pf1 = MLD(kl * 64 + b8 + 4, c0b, c1b);
    for (int c = 0; c < CHUNKS; c++) {
        __syncthreads();
        *(float4*)&Asm[kl][b8]     = pf0;
        *(float4*)&Asm[kl][b8 + 4] = pf1;
        __syncthreads();
        if (c < CHUNKS - 1) {
            int base = (c + 1) * 4096;
            pf0 = MLD(base + kl * 64 + b8, c0a, c1a);
            pf1 = MLD(base + kl * 64 + b8 + 4, c0b, c1b);
        }
        const float* wp = wp0 + (c * 64 + khalf * 32) * 32;
        #pragma unroll
        for (int kk = 0; kk < 32; kk++) {
            ull a = *(const ull*)&Asm[khalf * 32 + kk][2 * bp];
            ulonglong2 wv = *(const ulonglong2*)(wp + kk * 32);
            acc0 = fma2(a, wv.x, acc0);
            acc1 = fma2(a, wv.y, acc1);
        }
    }
    #undef MLD
}

// ---------------- persistent encoder (512 threads) ----------------
#define SMEM_ENC ((HH * 32 + 64 * 64) * 4)   // 48KB: splatted Wsm + Asm
__global__ void __launch_bounds__(TPB, 1) enc_persist() {
    extern __shared__ __align__(16) float dyn[];
    float* Wsm = dyn;                          // [256*32] splatted
    float (*Asm)[64] = (float(*)[64])(dyn + HH * 32);
    ull* cmb = (ull*)Asm;                      // reuse staging for k-half combine
    __shared__ float gsm[16][64];
    int blk = blockIdx.x, tid = threadIdx.x;
    int dir = blk >> 6, ub = blk & 63;
    for (int i = tid; i < 16 * HH; i += TPB) {
        int r = i >> 8, k = i & 255;
        float v = g_Whhp[((size_t)dir * G4H + ub * 16 + r) * HH + k];
        int base = k * 32 + (r >> 1) * 4 + (r & 1) * 2;
        Wsm[base] = v; Wsm[base + 1] = v;
    }
    __syncthreads();
    int lane = tid & 31;
    int w8 = (tid & 255) >> 5;
    int np = lane >> 2, bp = w8 * 4 + (lane & 3);
    int khalf = tid >> 8;
    int kl = tid >> 3, b8 = (tid & 7) << 3;
    int uu = tid >> 6, bc = tid & 63;          // cell (tid<256)
    const float* wp0 = Wsm + 4 * np;
    unsigned gen = bar_base();
    int p = 0;
    for (int t = 0; t < SS; t++) {
        const float* AT = g_hencT + ((size_t)p * 2 + dir) * HH * BB;
        ull acc0 = 0ull, acc1 = 0ull;
        wres2<4>(AT, wp0, Asm, bp, kl, b8, khalf, acc0, acc1);
        int s0 = dir ? (SS - 1 - t) : t;
        // combine k-halves
        __syncthreads();
        cmb[tid * 2] = acc0; cmb[tid * 2 + 1] = acc1;
        __syncthreads();
        if (tid < 256) {
            float2 a0 = unpack2(acc0), a1 = unpack2(acc1);
            float2 o0 = unpack2(cmb[(tid + 256) * 2]), o1 = unpack2(cmb[(tid + 256) * 2 + 1]);
            a0.x += o0.x; a0.y += o0.y; a1.x += o1.x; a1.y += o1.y;
            const float* gx = (dir ? g_gxb : g_gxf) + ((size_t)s0 * G4H + ub * 16) * 64;
            float2 g0 = *(const float2*)&gx[(2 * np) * 64 + 2 * bp];
            float2 g1 = *(const float2*)&gx[(2 * np + 1) * 64 + 2 * bp];
            *(float2*)&gsm[2 * np][2 * bp]     = make_float2(a0.x + g0.x, a0.y + g0.y);
            *(float2*)&gsm[2 * np + 1][2 * bp] = make_float2(a1.x + g1.x, a1.y + g1.y);
        }
        __syncthreads();
        if (tid < 256) {
            float gi = gsm[uu][bc], gf = gsm[4 + uu][bc], gg = gsm[8 + uu][bc], go = gsm[12 + uu][bc];
            int u = ub * 4 + uu;
            size_t ci = ((size_t)dir * HH + u) * BB + bc;
            float c = g_cencT[ci];
            c = sigf(gf) * c + sigf(gi) * tanhf(gg);
            float hn = sigf(go) * tanhf(c);
            g_cencT[ci] = c;
            g_hencT[((size_t)(p ^ 1) * 2 + dir) * HH * BB + (size_t)u * BB + bc] = hn;
            g_h[((size_t)s0 * BB + bc) * DHH + dir * HH + u] = hn;
        }
        p ^= 1;
        gsync2(blk, ++gen);
    }
}

// ---------------- persistent decoder (512 threads) ----------------
#define SMEM_DEC ((1024 * 32 + 64 * 64) * 4)   // 144KB: splatted Wsm + Asm
__global__ void __launch_bounds__(TPB, 1) dec_persist(int l0, int l1) {
    extern __shared__ __align__(16) float dyn[];
    float* Wsm = dyn;                           // [1024*32] splatted
    float (*Asm)[64] = (float(*)[64])(dyn + 1024 * 32);
    ull* cmb = (ull*)Asm;                       // reuse staging for k-half combine
    __shared__ float gsm[16][64];
    __shared__ __align__(16) float hd_s[DHH];
    __shared__ float sc[64];
    __shared__ float red[64];
    __shared__ __align__(16) float c0sm[64], c1sm[64];
    int blk = blockIdx.x, tid = threadIdx.x;
    int half = blk & 1, ab = blk >> 1;          // attention: 2 blocks per batch
    for (int i = tid; i < 16 * 1024; i += TPB) {
        int r = i >> 10, k = i & 1023;
        float v = g_Wcat[((size_t)blk * 16 + r) * 1024 + k];
        int base = k * 32 + (r >> 1) * 4 + (r & 1) * 2;
        Wsm[base] = v; Wsm[base + 1] = v;
    }
    __syncthreads();
    int lane = tid & 31;
    int w16 = tid >> 5;                         // 0..15
    int w8 = (tid & 255) >> 5;
    int np = lane >> 2, bp = w8 * 4 + (lane & 3);
    int khalf = tid >> 8;
    int kl = tid >> 3, b8 = (tid & 7) << 3;
    int uu = tid >> 6, bc = tid & 63;           // cell (tid<256)
    const float* wpA = Wsm + 512 * 32 + 4 * np;   // hd half (k 512..1023)
    const float* wpB = Wsm + 4 * np;              // ctx half (k 0..511)
    unsigned gen = bar_base();
    for (int lvl = l0; lvl < l1; lvl++) {
        const float* pre = (lvl == 0) ? g_pre0 : g_pre1;
        float oh0 = g_ohcp[lvl * GD + blk * 16 + 2 * np];
        float oh1 = g_ohcp[lvl * GD + blk * 16 + 2 * np + 1];
        for (int t = 0; t < SS; t++) {
            // ===== phase A: attention half first (L2-bound), then hd-half GEMM =====
            {
                for (int i = tid; i < DHH; i += TPB) hd_s[i] = g_hd[ab * DHH + i];
                __syncthreads();
                for (int it = 0; it < 4; it++) {
                    int s_loc = w16 * 4 + it;
                    int s = half * 64 + s_loc;
                    const float4* w4 = (const float4*)(g_wh + ((size_t)s * BB + ab) * DHH);
                    const float4* h4 = (const float4*)hd_s;
                    float sum = 0.f;
                    #pragma unroll
                    for (int qq = 0; qq < 4; qq++) {
                        float4 a = w4[lane * 4 + qq];
                        float4 c = h4[lane * 4 + qq];
                        sum += a.x * c.x + a.y * c.y + a.z * c.z + a.w * c.w;
                    }
                    #pragma unroll
                    for (int off = 16; off; off >>= 1) sum += __shfl_xor_sync(0xffffffffu, sum, off);
                    if (lane == 0) sc[s_loc] = sum;
                }
                __syncthreads();
                if (tid < 64) red[tid] = sc[tid];
                __syncthreads();
                for (int off = 32; off; off >>= 1) {
                    if (tid < off) red[tid] = fmaxf(red[tid], red[tid + off]);
                    __syncthreads();
                }
                float mx = red[0];
                __syncthreads();
                if (tid < 64) { float e = __expf(sc[tid] - mx); sc[tid] = e; red[tid] = e; }
                __syncthreads();
                for (int off = 32; off; off >>= 1) {
                    if (tid < off) red[tid] += red[tid + off];
                    __syncthreads();
                }
                if (tid == 0) { g_attM[ab * 2 + half] = mx; g_attS[ab * 2 + half] = red[0]; }
                // partial unnormalized ctx over this half's 64 s (1 d per thread)
                {
                    int d = tid;
                    float acc = 0.f;
                    #pragma unroll 8
                    for (int s_loc = 0; s_loc < 64; s_loc++)
                        acc += sc[s_loc] * g_h[(((size_t)(half * 64 + s_loc)) * BB + ab) * DHH + d];
                    g_ctxP[((size_t)half * DHH + d) * 64 + ab] = acc;
                }
                __syncthreads();
            }
            ull acc0 = 0ull, acc1 = 0ull;
            wres2<8>(g_hdT, wpA, Asm, bp, kl, b8, khalf, acc0, acc1);
            gsync2(blk, ++gen);
            // ===== phase B: flash-merge + ctx-half GEMM + combine + cell =====
            if (tid < 64) {
                float m0 = g_attM[tid * 2], m1 = g_attM[tid * 2 + 1];
                float M = fmaxf(m0, m1);
                float e0 = __expf(m0 - M), e1 = __expf(m1 - M);
                float den = g_attS[tid * 2] * e0 + g_attS[tid * 2 + 1] * e1;
                c0sm[tid] = e0 / den;
                c1sm[tid] = e1 / den;
            }
            __syncthreads();
            float4 c0a = *(const float4*)&c0sm[b8];
            float4 c0b = *(const float4*)&c0sm[b8 + 4];
            float4 c1a = *(const float4*)&c1sm[b8];
            float4 c1b = *(const float4*)&c1sm[b8 + 4];
            wres2m<8>(g_ctxP, g_ctxP + DHH * 64, c0a, c1a, c0b, c1b,
                      wpB, Asm, bp, kl, b8, khalf, acc0, acc1);
            // combine k-halves
            __syncthreads();
            cmb[tid * 2] = acc0; cmb[tid * 2 + 1] = acc1;
            __syncthreads();
            if (tid < 256) {
                float2 a0 = unpack2(acc0), a1 = unpack2(acc1);
                float2 o0 = unpack2(cmb[(tid + 256) * 2]), o1 = unpack2(cmb[(tid + 256) * 2 + 1]);
                a0.x += o0.x; a0.y += o0.y; a1.x += o1.x; a1.y += o1.y;
                const float* pr = pre + ((size_t)t * GD + blk * 16) * 64;
                float2 p0 = *(const float2*)&pr[(2 * np) * 64 + 2 * bp];
                float2 p1 = *(const float2*)&pr[(2 * np + 1) * 64 + 2 * bp];
                *(float2*)&gsm[2 * np][2 * bp]     = make_float2(a0.x + p0.x + oh0, a0.y + p0.y + oh0);
                *(float2*)&gsm[2 * np + 1][2 * bp] = make_float2(a1.x + p1.x + oh1, a1.y + p1.y + oh1);
            }
            __syncthreads();
            if (tid < 256) {
                float gi = gsm[uu][bc], gf = gsm[4 + uu][bc], gg = gsm[8 + uu][bc], go = gsm[12 + uu][bc];
                int u = blk * 4 + uu;
                size_t ci = (size_t)u * BB + bc;
                float c = g_cdT[ci];
                c = sigf(gf) * c + sigf(gi) * tanhf(gg);
                float hn = sigf(go) * tanhf(c);
                g_cdT[ci] = c;
                g_hdT[ci] = hn;
                g_hd[(size_t)bc * DHH + u] = hn;
                g_dout[(((size_t)lvl * SS + t) * BB + bc) * DHH + u] = hn;
            }
            gsync2(blk, ++gen);
        }
    }
}

// ---------------- output projection ----------------
__global__ void out_proj(const float* __restrict__ W2, const float* __restrict__ b2,
                         float* __restrict__ out) {
    int m = blockIdx.x;
    int lane = threadIdx.x;
    const float* drow = g_dout + (size_t)m * DHH;
    float acc[CC] = {};
    for (int k = lane; k < DHH; k += 32) {
        float d = drow[k];
        #pragma unroll
        for (int c = 0; c < CC; c++) acc[c] += d * W2[c * DHH + k];
    }
    #pragma unroll
    for (int c = 0; c < CC; c++) {
        float v = acc[c];
        #pragma unroll
        for (int off = 16; off; off >>= 1) v += __shfl_xor_sync(0xffffffffu, v, off);
        if (lane == 0) out[(size_t)m * CC + c] = v + b2[c];
    }
}

// ---------------- host ----------------
extern "C" void kernel_launch(void* const* d_in, const int* in_sizes, int n_in,
                              void* d_out, int out_size) {
    const int*   seqs  = (const int*)d_in[0];
    const float* emb   = (const float*)d_in[2];
    const float* Wih_f = (const float*)d_in[3];
    const float* Whh_f = (const float*)d_in[4];
    const float* bih_f = (const float*)d_in[5];
    const float* bhh_f = (const float*)d_in[6];
    const float* Wih_b = (const float*)d_in[7];
    const float* Whh_b = (const float*)d_in[8];
    const float* bih_b = (const float*)d_in[9];
    const float* bhh_b = (const float*)d_in[10];
    const float* Wl    = (const float*)d_in[11];
    const float* Wih_d = (const float*)d_in[12];
    const float* Whh_d = (const float*)d_in[13];
    const float* bih_d = (const float*)d_in[14];
    const float* bhh_d = (const float*)d_in[15];
    const float* W2    = (const float*)d_in[16];
    const float* b2    = (const float*)d_in[17];
    float* out = (float*)d_out;

    cudaFuncSetAttribute(enc_persist, cudaFuncAttributeMaxDynamicSharedMemorySize, SMEM_ENC);
    cudaFuncSetAttribute(dec_persist, cudaFuncAttributeMaxDynamicSharedMemorySize, SMEM_DEC);

    // 0: prep
    k_prep<<<(PREP_TOTAL + 255) / 256, 256>>>(Whh_f, Whh_b, Wih_f, Wih_b,
                                              bih_f, bhh_f, bih_b, bhh_b,
                                              Wih_d, Whh_d, bih_d, bhh_d);
    // 1: embed
    k_embed<<<SS * BB, 128>>>(seqs, emb);
    // 2: encoder input GEMMs (both dirs, transposed out)
    k_encg<<<dim3(SS * BB / 64, G4H / 64, 2), 256>>>();
    // 3: encoder recurrence (512 threads)
    enc_persist<<<NBE, TPB, SMEM_ENC>>>();
    // 4: pre0 (+bias, transposed) and wh, one launch
    k_pre<<<dim3(SS * BB / 64, 40), 256>>>(Wl);
    // 5: decoder level 0 (512 threads)
    dec_persist<<<NBD, TPB, SMEM_DEC>>>(0, 1);
    // 6: pre1 = pre0 + (dout0 - h)@Wprev
    k_pre1<<<dim3(SS * BB / 64, GD / 64), 256>>>();
    // 7: decoder levels 1-3
    dec_persist<<<NBD, TPB, SMEM_DEC>>>(1, 4);
    // 8: logits
    out_proj<<<LMAXX * SS * BB, 32>>>(W2, b2, out);
}

// round 15
// speedup vs baseline: 1.1593x; 1.1499x over previous
#include <cuda_runtime.h>
#include <math.h>

// ---------------- problem dims ----------------
#define SS    128
#define BB    64
#define EE    512
#define HH    256
#define DHH   512
#define G4H   1024
#define GD    2048
#define LDWD  2052
#define LMAXX 4
#define CC    9

#define NBE   128
#define NBD   128
#define TPB   512

typedef unsigned long long ull;

// gate-locality permutations: block owns all 4 gates of 4 units
__device__ __forceinline__ int enperm(int np) { return (((np >> 2) & 3) << 8) + ((np >> 4) << 2) + (np & 3); }
__device__ __forceinline__ int deperm(int np) { return (((np >> 2) & 3) << 9) + ((np >> 4) << 2) + (np & 3); }

// ---------------- static device scratch ----------------
__device__ float g_x   [SS*BB*EE];
__device__ float g_gxf [SS*BB*G4H];      // TRANSPOSED: [s][np][b]
__device__ float g_gxb [SS*BB*G4H];
__device__ float g_h   [SS*BB*DHH];      // [s][b][d]
__device__ float g_wh  [SS*BB*DHH];      // [s][b][d]
__device__ float g_pre0[SS*BB*GD];       // TRANSPOSED: [t][np][b]
__device__ float g_pre1[SS*BB*GD];
__device__ float g_dout[LMAXX*SS*BB*DHH];
__device__ float g_hencT[2*2*HH*BB];     // [p][dir][u][b]
__device__ float g_cencT[2*HH*BB];
__device__ float g_hd  [BB*DHH];         // [b][u]
__device__ float g_hdT [DHH*BB];         // [u][b]
__device__ float g_cdT [DHH*BB];
__device__ float g_ctxP[2*DHH*BB];       // [half][d][b]
__device__ float g_attM[2*BB];
__device__ float g_attS[2*BB];
__device__ float g_Whhp[2*G4H*HH];       // permuted rows [dir][np][k]
__device__ float g_Wihp[2*G4H*EE];
__device__ float g_bep [2*G4H];
__device__ float g_Wcat[GD*1024];        // permuted rows: [Wih_d[:, :512] | Whh_d]
__device__ float g_Wmid0[GD*1024];       // permuted rows: Wih_d[:,512:1536], h-cols += Wprev
__device__ float g_Wprev[GD*DHH];
__device__ float g_bdp [GD];
__device__ float g_ohcp[LMAXX*GD];

// ---------------- flag-tree grid barrier ----------------
__device__ unsigned g_flags[NBD * 32];
__device__ unsigned g_rel;

__device__ __forceinline__ unsigned bar_base() {
    unsigned v;
    asm volatile("ld.global.u32 %0, [%1];" : "=r"(v) : "l"(&g_rel));
    return v;
}

__device__ __forceinline__ void gsync2(int blk, unsigned gen) {
    __syncthreads();
    if (threadIdx.x == 0)
        asm volatile("st.release.gpu.u32 [%0], %1;" :: "l"(&g_flags[blk * 32]), "r"(gen) : "memory");
    if (blk == 0) {
        if (threadIdx.x < NBD) {
            unsigned v;
            while (true) {
                asm volatile("ld.acquire.gpu.u32 %0, [%1];" : "=r"(v) : "l"(&g_flags[threadIdx.x * 32]) : "memory");
                if ((int)(v - gen) >= 0) break;
                __nanosleep(64);
            }
        }
        __syncthreads();
        if (threadIdx.x == 0)
            asm volatile("st.release.gpu.u32 [%0], %1;" :: "l"(&g_rel), "r"(gen) : "memory");
    } else if (threadIdx.x == 0) {
        unsigned v;
        while (true) {
            asm volatile("ld.acquire.gpu.u32 %0, [%1];" : "=r"(v) : "l"(&g_rel) : "memory");
            if ((int)(v - gen) >= 0) break;
            __nanosleep(64);
        }
    }
    __syncthreads();
}

__device__ __forceinline__ float sigf(float x) { return 1.0f / (1.0f + __expf(-x)); }

__device__ __forceinline__ ull fma2(ull a, ull b, ull c) {
    ull d;
    asm("fma.rn.f32x2 %0, %1, %2, %3;" : "=l"(d) : "l"(a), "l"(b), "l"(c));
    return d;
}
__device__ __forceinline__ float2 unpack2(ull v) {
    float2 r;
    asm("mov.b64 {%0, %1}, %2;" : "=f"(r.x), "=f"(r.y) : "l"(v));
    return r;
}
__device__ __forceinline__ ull splat2(float v) {
    ull r;
    asm("mov.b64 %0, {%1, %1};" : "=l"(r) : "f"(v));
    return r;
}

// ---------------- prep (includes embed) ----------------
#define EMB_TOTAL (SS*BB*EE)
#define Z_TOTAL 196608
#define PREP_TOTAL (EMB_TOTAL + Z_TOTAL + 524288 + 1048576 + 2048 + 2097152 + 2097152 + 1048576 + 2048 + 8192)
__global__ void k_prep(const int* __restrict__ seqs, const float* __restrict__ emb,
                       const float* __restrict__ Whh_f, const float* __restrict__ Whh_b,
                       const float* __restrict__ Wih_f, const float* __restrict__ Wih_b,
                       const float* __restrict__ bih_f, const float* __restrict__ bhh_f,
                       const float* __restrict__ bih_b, const float* __restrict__ bhh_b,
                       const float* __restrict__ Wih_d, const float* __restrict__ Whh_d,
                       const float* __restrict__ bih_d, const float* __restrict__ bhh_d) {
    long long i = (long long)blockIdx.x * 256 + threadIdx.x;
    if (i < EMB_TOTAL) { // embed
        int m = (int)(i >> 9), e = (int)(i & 511);
        int s = m >> 6, b = m & 63;
        g_x[i] = emb[(size_t)seqs[b * SS + s] * EE + e];
        return;
    }
    i -= EMB_TOTAL;
    if (i < Z_TOTAL) {
        if (i < 65536) g_hencT[i] = 0.f;
        else if (i < 98304) g_cencT[i - 65536] = 0.f;
        else if (i < 131072) g_hd[i - 98304] = 0.f;
        else if (i < 163840) g_hdT[i - 131072] = 0.f;
        else g_cdT[i - 163840] = 0.f;
        return;
    }
    i -= Z_TOTAL;
    if (i < 524288) { // Whhp
        int dir = (int)(i >> 18), r = (int)(i & 262143);
        int np = r >> 8, k = r & 255;
        int n = enperm(np);
        g_Whhp[i] = (dir ? Whh_b : Whh_f)[n * HH + k];
        return;
    }
    i -= 524288;
    if (i < 1048576) { // Wihp
        int dir = (int)(i >> 19), r = (int)(i & 524287);
        int np = r >> 9, k = r & 511;
        int n = enperm(np);
        g_Wihp[i] = (dir ? Wih_b : Wih_f)[n * EE + k];
        return;
    }
    i -= 1048576;
    if (i < 2048) { // encoder bias
        int dir = (int)(i >> 10), np = (int)(i & 1023);
        int n = enperm(np);
        g_bep[i] = dir ? (bih_b[n] + bhh_b[n]) : (bih_f[n] + bhh_f[n]);
        return;
    }
    i -= 2048;
    if (i < 2097152) { // Wcat
        int np = (int)(i >> 10), k = (int)(i & 1023);
        int n = deperm(np);
        g_Wcat[i] = (k < 512) ? Wih_d[(size_t)n * LDWD + k] : Whh_d[(size_t)n * DHH + (k - 512)];
        return;
    }
    i -= 2097152;
    if (i < 2097152) { // Wmid0
        int np = (int)(i >> 10), k = (int)(i & 1023);
        int n = deperm(np);
        float v = Wih_d[(size_t)n * LDWD + 512 + k];
        if (k < 512) v += Wih_d[(size_t)n * LDWD + 1536 + k];
        g_Wmid0[i] = v;
        return;
    }
    i -= 2097152;
    if (i < 1048576) { // Wprev
        int np = (int)(i >> 9), k = (int)(i & 511);
        int n = deperm(np);
        g_Wprev[i] = Wih_d[(size_t)n * LDWD + 1536 + k];
        return;
    }
    i -= 1048576;
    if (i < 2048) { // decoder bias
        int n = deperm((int)i);
        g_bdp[i] = bih_d[n] + bhh_d[n];
        return;
    }
    i -= 2048;
    if (i < 8192) { // one-hot columns
        int lvl = (int)(i >> 11), np = (int)(i & 2047);
        int n = deperm(np);
        g_ohcp[i] = Wih_d[(size_t)n * LDWD + GD + lvl];
        return;
    }
}

// ---------------- precompute GEMM cores ----------------
// 256-thread version with static smem (k_encg, k_pre1)
__device__ __forceinline__ void gemm_body(float (*As)[68], float (*Ws)[68], int tid,
                        const float* __restrict__ A, int lda,
                        const float* __restrict__ A2, const float* __restrict__ Asub,
                        const float* __restrict__ W, int ldw,
                        float* __restrict__ C, int N, int K,
                        const float* __restrict__ add, const float* __restrict__ bias,
                        int tpose, int m0, int n0, int barid) {
    int tm = (tid >> 4) << 2, tn = (tid & 15) << 2;
    float acc[4][4] = {};
    for (int k0 = 0; k0 < K; k0 += 16) {
        const float* Asrc = A;
        int kk0 = k0;
        bool second = (A2 && k0 >= 512);
        if (second) { Asrc = A2; kk0 = k0 - 512; }
        #pragma unroll
        for (int i = tid; i < 1024; i += 256) {
            int r = i >> 4, k = i & 15;
            float v = Asrc[(size_t)(m0 + r) * lda + kk0 + k];
            if (Asub && !second) v -= Asub[(size_t)(m0 + r) * lda + kk0 + k];
            As[k][r] = v;
            Ws[k][r] = W[(size_t)(n0 + r) * ldw + k0 + k];
        }
        asm volatile("bar.sync %0, 256;" :: "r"(barid) : "memory");
        #pragma unroll
        for (int k = 0; k < 16; k++) {
            float4 a4 = *(const float4*)&As[k][tm];
            float4 w4 = *(const float4*)&Ws[k][tn];
            acc[0][0] += a4.x * w4.x; acc[0][1] += a4.x * w4.y; acc[0][2] += a4.x * w4.z; acc[0][3] += a4.x * w4.w;
            acc[1][0] += a4.y * w4.x; acc[1][1] += a4.y * w4.y; acc[1][2] += a4.y * w4.z; acc[1][3] += a4.y * w4.w;
            acc[2][0] += a4.z * w4.x; acc[2][1] += a4.z * w4.y; acc[2][2] += a4.z * w4.z; acc[2][3] += a4.z * w4.w;
            acc[3][0] += a4.w * w4.x; acc[3][1] += a4.w * w4.y; acc[3][2] += a4.w * w4.z; acc[3][3] += a4.w * w4.w;
        }
        asm volatile("bar.sync %0, 256;" :: "r"(barid) : "memory");
    }
    #pragma unroll
    for (int i = 0; i < 4; i++)
        #pragma unroll
        for (int j = 0; j < 4; j++) {
            int m = m0 + tm + i, n = n0 + tn + j;
            float v = acc[i][j];
            if (bias) v += bias[n];
            if (tpose) {
                size_t idx = ((size_t)(m >> 6) * N + n) * 64 + (m & 63);
                if (add) v += add[idx];
                C[idx] = v;
            } else {
                size_t idx = (size_t)m * N + n;
                if (add) v += add[idx];
                C[idx] = v;
            }
        }
}

__global__ void __launch_bounds__(256) k_encg() {
    __shared__ __align__(16) float As[16][68];
    __shared__ __align__(16) float Ws[16][68];
    int z = blockIdx.z;
    gemm_body(As, Ws, threadIdx.x, g_x, EE, nullptr, nullptr,
              g_Wihp + (size_t)z * G4H * EE, EE,
              z ? g_gxb : g_gxf, G4H, EE,
              nullptr, g_bep + z * G4H, 1,
              blockIdx.x * 64, blockIdx.y * 64, 0);
}

__global__ void __launch_bounds__(256) k_pre1() {
    __shared__ __align__(16) float As[16][68];
    __shared__ __align__(16) float Ws[16][68];
    gemm_body(As, Ws, threadIdx.x, g_dout, DHH, nullptr, g_h, g_Wprev, DHH, g_pre1, GD, DHH,
              g_pre0, nullptr, 1, blockIdx.x * 64, blockIdx.y * 64, 0);
}

// ---------------- register-tiled W-resident GEMM ----------------
// Warp w = kseg; lane: ntile=lane>>3 (4 n per tile), btile=lane&7 (4 b-pairs per tile).
// Per chunk (64 staged k), warp handles k = c*64 + w*4 .. +3. acc[4n][4bp] f32x2.
template<int CHUNKS>
__device__ __forceinline__ void wres_rt(const float* __restrict__ AT,
                                        const float* __restrict__ Wk,
                                        float (*Asm)[64],
                                        int w, int ntile, int btile, int kl, int b8,
                                        ull acc[4][4]) {
    float4 pf0 = *(const float4*)&AT[kl * 64 + b8];
    float4 pf1 = *(const float4*)&AT[kl * 64 + b8 + 4];
    for (int c = 0; c < CHUNKS; c++) {
        __syncthreads();
        *(float4*)&Asm[kl][b8]     = pf0;
        *(float4*)&Asm[kl][b8 + 4] = pf1;
        __syncthreads();
        if (c < CHUNKS - 1) {
            const float* src = AT + (c + 1) * 4096;
            pf0 = *(const float4*)&src[kl * 64 + b8];
            pf1 = *(const float4*)&src[kl * 64 + b8 + 4];
        }
        const float* wrow = Wk + (c * 64 + w * 4) * 16 + ntile * 4;
        #pragma unroll
        for (int kk = 0; kk < 4; kk++) {
            float4 wv = *(const float4*)(wrow + kk * 16);
            ull w0 = splat2(wv.x), w1 = splat2(wv.y), w2 = splat2(wv.z), w3 = splat2(wv.w);
            const ull* ap = (const ull*)&Asm[w * 4 + kk][btile * 8];
            ull a0 = ap[0], a1 = ap[1], a2 = ap[2], a3 = ap[3];
            acc[0][0] = fma2(a0, w0, acc[0][0]); acc[0][1] = fma2(a1, w0, acc[0][1]);
            acc[0][2] = fma2(a2, w0, acc[0][2]); acc[0][3] = fma2(a3, w0, acc[0][3]);
            acc[1][0] = fma2(a0, w1, acc[1][0]); acc[1][1] = fma2(a1, w1, acc[1][1]);
            acc[1][2] = fma2(a2, w1, acc[1][2]); acc[1][3] = fma2(a3, w1, acc[1][3]);
            acc[2][0] = fma2(a0, w2, acc[2][0]); acc[2][1] = fma2(a1, w2, acc[2][1]);
            acc[2][2] = fma2(a2, w2, acc[2][2]); acc[2][3] = fma2(a3, w2, acc[2][3]);
            acc[3][0] = fma2(a0, w3, acc[3][0]); acc[3][1] = fma2(a1, w3, acc[3][1]);
            acc[3][2] = fma2(a2, w3, acc[3][2]); acc[3][3] = fma2(a3, w3, acc[3][3]);
        }
    }
}

// merged-fill variant (flash-softmax ctx merge)
template<int CHUNKS>
__device__ __forceinline__ void wres_rtm(const float* __restrict__ P0,
                                         const float* __restrict__ P1,
                                         float4 c0a, float4 c1a, float4 c0b, float4 c1b,
                                         const float* __restrict__ Wk,
                                         float (*Asm)[64],
                                         int w, int ntile, int btile, int kl, int b8,
                                         ull acc[4][4]) {
    #define MLD(off, c0, c1) ({ float4 x0 = *(const float4*)&P0[off]; \
                        float4 x1 = *(const float4*)&P1[off]; \
                        float4 r; \
                        r.x = x0.x * c0.x + x1.x * c1.x; \
                        r.y = x0.y * c0.y + x1.y * c1.y; \
                        r.z = x0.z * c0.z + x1.z * c1.z; \
                        r.w = x0.w * c0.w + x1.w * c1.w; r; })
    float4 pf0 = MLD(kl * 64 + b8, c0a, c1a);
    float4 pf1 = MLD(kl * 64 + b8 + 4, c0b, c1b);
    for (int c = 0; c < CHUNKS; c++) {
        __syncthreads();
        *(float4*)&Asm[kl][b8]     = pf0;
        *(float4*)&Asm[kl][b8 + 4] = pf1;
        __syncthreads();
        if (c < CHUNKS - 1) {
            int base = (c + 1) * 4096;
            pf0 = MLD(base + kl * 64 + b8, c0a, c1a);
            pf1 = MLD(base + kl * 64 + b8 + 4, c0b, c1b);
        }
        const float* wrow = Wk + (c * 64 + w * 4) * 16 + ntile * 4;
        #pragma unroll
        for (int kk = 0; kk < 4; kk++) {
            float4 wv = *(const float4*)(wrow + kk * 16);
            ull w0 = splat2(wv.x), w1 = splat2(wv.y), w2 = splat2(wv.z), w3 = splat2(wv.w);
            const ull* ap = (const ull*)&Asm[w * 4 + kk][btile * 8];
            ull a0 = ap[0], a1 = ap[1], a2 = ap[2], a3 = ap[3];
            acc[0][0] = fma2(a0, w0, acc[0][0]); acc[0][1] = fma2(a1, w0, acc[0][1]);
            acc[0][2] = fma2(a2, w0, acc[0][2]); acc[0][3] = fma2(a3, w0, acc[0][3]);
            acc[1][0] = fma2(a0, w1, acc[1][0]); acc[1][1] = fma2(a1, w1, acc[1][1]);
            acc[1][2] = fma2(a2, w1, acc[1][2]); acc[1][3] = fma2(a3, w1, acc[1][3]);
            acc[2][0] = fma2(a0, w2, acc[2][0]); acc[2][1] = fma2(a1, w2, acc[2][1]);
            acc[2][2] = fma2(a2, w2, acc[2][2]); acc[2][3] = fma2(a3, w2, acc[2][3]);
            acc[3][0] = fma2(a0, w3, acc[3][0]); acc[3][1] = fma2(a1, w3, acc[3][1]);
            acc[3][2] = fma2(a2, w3, acc[3][2]); acc[3][3] = fma2(a3, w3, acc[3][3]);
        }
    }
    #undef MLD
}

// stage per-warp accs into Csm and reduce over 16 warps; returns float2 for (n=tid>>5, bp=tid&31)
__device__ __forceinline__ float2 kseg_combine(float* Csm, ull acc[4][4],
                                               int w, int ntile, int btile, int tid) {
    __syncthreads();   // all compute done; Asm region reusable
    ull* Cu = (ull*)Csm;
    #pragma unroll
    for (int i = 0; i < 4; i++)
        #pragma unroll
        for (int j = 0; j < 4; j++)
            Cu[w * 512 + (ntile * 4 + i) * 32 + (btile * 4 + j)] = acc[i][j];
    __syncthreads();
    float2 s = make_float2(0.f, 0.f);
    #pragma unroll
    for (int ww = 0; ww < 16; ww++) {
        float2 v = unpack2(Cu[ww * 512 + tid]);
        s.x += v.x; s.y += v.y;
    }
    return s;
}

// ---------------- persistent encoder (+ fused pre0/wh tail) ----------------
#define SMEM_ENC ((HH*16 + 16*1024) * 4)   // Wsm 16KB + Csm 64KB (Asm overlays Csm front)
__global__ void __launch_bounds__(TPB, 1) enc_persist(const float* __restrict__ Wl) {
    extern __shared__ __align__(16) float dyn[];
    float* Wsm = dyn;                        // [256][16]
    float* Csm = dyn + HH * 16;              // 16K floats
    float (*Asm)[64] = (float(*)[64])Csm;    // front 16KB
    __shared__ float gsm[16][64];
    int blk = blockIdx.x, tid = threadIdx.x;
    int dir = blk >> 6, ub = blk & 63;
    for (int i = tid; i < 16 * HH; i += TPB) {
        int r = i >> 8, k = i & 255;
        Wsm[k * 16 + r] = g_Whhp[((size_t)dir * G4H + ub * 16 + r) * HH + k];
    }
    __syncthreads();
    int lane = tid & 31, w = tid >> 5;
    int ntile = lane >> 3, btile = lane & 7;
    int kl = tid >> 3, b8 = (tid & 7) << 3;
    int uu = tid >> 6, bc = tid & 63;        // cell (tid<256)
    unsigned gen = bar_base();
    int p = 0;
    for (int t = 0; t < SS; t++) {
        const float* AT = g_hencT + ((size_t)p * 2 + dir) * HH * BB;
        ull acc[4][4] = {};
        wres_rt<4>(AT, Wsm, Asm, w, ntile, btile, kl, b8, acc);
        float2 s = kseg_combine(Csm, acc, w, ntile, btile, tid);
        int s0 = dir ? (SS - 1 - t) : t;
        {
            int n = tid >> 5, bp = tid & 31;
            const float* gx = (dir ? g_gxb : g_gxf) + ((size_t)s0 * G4H + ub * 16 + n) * 64;
            float2 g2 = *(const float2*)&gx[2 * bp];
            *(float2*)&gsm[n][2 * bp] = make_float2(s.x + g2.x, s.y + g2.y);
        }
        __syncthreads();
        if (tid < 256) {
            float gi = gsm[uu][bc], gf = gsm[4 + uu][bc], gg = gsm[8 + uu][bc], go = gsm[12 + uu][bc];
            int u = ub * 4 + uu;
            size_t ci = ((size_t)dir * HH + u) * BB + bc;
            float c = g_cencT[ci];
            c = sigf(gf) * c + sigf(gi) * tanhf(gg);
            float hn = sigf(go) * tanhf(c);
            g_cencT[ci] = c;
            g_hencT[((size_t)(p ^ 1) * 2 + dir) * HH * BB + (size_t)u * BB + bc] = hn;
            g_h[((size_t)s0 * BB + bc) * DHH + dir * HH + u] = hn;
        }
        p ^= 1;
        gsync2(blk, ++gen);
    }
    // ---- fused tail: pre0 = [h|x]@Wmid0+bd (4096 tiles) and wh = h@Wl (1024 tiles) ----
    {
        int hh = tid >> 8;                 // half 0/1
        int t256 = tid & 255;
        float (*As)[68] = (float(*)[68])(dyn + hh * 2432);
        float (*Ws)[68] = (float(*)[68])(dyn + hh * 2432 + 1120);
        for (int i = 0; i < 20; i++) {
            int T = blk * 40 + hh * 20 + i;
            if (T < 4096) {
                gemm_body(As, Ws, t256, g_h, DHH, g_x, nullptr, g_Wmid0, 1024,
                          g_pre0, GD, 1024, nullptr, g_bdp, 1,
                          (T >> 5) * 64, (T & 31) * 64, 1 + hh);
            } else {
                int t2 = T - 4096;
                gemm_body(As, Ws, t256, g_h, DHH, nullptr, nullptr, Wl, DHH,
                          g_wh, DHH, DHH, nullptr, nullptr, 0,
                          (t2 >> 3) * 64, (t2 & 7) * 64, 1 + hh);
            }
        }
    }
}

// ---------------- persistent decoder ----------------
#define SMEM_DEC ((1024*16 + 16*1024) * 4)  // Wsm 64KB + Csm 64KB = 128KB
__global__ void __launch_bounds__(TPB, 1) dec_persist(int l0, int l1) {
    extern __shared__ __align__(16) float dyn[];
    float* Wsm = dyn;                        // [1024][16]
    float* Csm = dyn + 1024 * 16;
    float (*Asm)[64] = (float(*)[64])Csm;
    __shared__ float gsm[16][64];
    __shared__ __align__(16) float hd_s[DHH];
    __shared__ float sc[64];
    __shared__ __align__(16) float c0sm[64], c1sm[64];
    int blk = blockIdx.x, tid = threadIdx.x;
    int half = blk & 1, ab = blk >> 1;
    for (int i = tid; i < 16 * 1024; i += TPB) {
        int r = i >> 10, k = i & 1023;
        Wsm[k * 16 + r] = g_Wcat[((size_t)blk * 16 + r) * 1024 + k];
    }
    __syncthreads();
    int lane = tid & 31, w = tid >> 5;
    int ntile = lane >> 3, btile = lane & 7;
    int kl = tid >> 3, b8 = (tid & 7) << 3;
    int uu = tid >> 6, bc = tid & 63;
    const float* WkA = Wsm + 512 * 16;       // hd half (k 512..1023)
    const float* WkB = Wsm;                  // ctx half (k 0..511)
    unsigned gen = bar_base();
    for (int lvl = l0; lvl < l1; lvl++) {
        const float* pre = (lvl == 0) ? g_pre0 : g_pre1;
        float ohn = g_ohcp[lvl * GD + blk * 16 + (tid >> 5)];
        for (int t = 0; t < SS; t++) {
            // ===== phase A: attention half, then hd-half GEMM =====
            {
                for (int i = tid; i < DHH; i += TPB) hd_s[i] = g_hd[ab * DHH + i];
                __syncthreads();
                for (int it = 0; it < 4; it++) {
                    int s_loc = w * 4 + it;
                    int s = half * 64 + s_loc;
                    const float4* w4 = (const float4*)(g_wh + ((size_t)s * BB + ab) * DHH);
                    const float4* h4 = (const float4*)hd_s;
                    float sum = 0.f;
                    #pragma unroll
                    for (int qq = 0; qq < 4; qq++) {
                        float4 a = w4[lane * 4 + qq];
                        float4 c = h4[lane * 4 + qq];
                        sum += a.x * c.x + a.y * c.y + a.z * c.z + a.w * c.w;
                    }
                    #pragma unroll
                    for (int off = 16; off; off >>= 1) sum += __shfl_xor_sync(0xffffffffu, sum, off);
                    if (lane == 0) sc[s_loc] = sum;
                }
                __syncthreads();
                if (w == 0) {   // single-warp softmax over 64 scores
                    float v0 = sc[lane], v1 = sc[lane + 32];
                    float m = fmaxf(v0, v1);
                    #pragma unroll
                    for (int off = 16; off; off >>= 1) m = fmaxf(m, __shfl_xor_sync(0xffffffffu, m, off));
                    float e0 = __expf(v0 - m), e1 = __expf(v1 - m);
                    float ssum = e0 + e1;
                    #pragma unroll
                    for (int off = 16; off; off >>= 1) ssum += __shfl_xor_sync(0xffffffffu, ssum, off);
                    sc[lane] = e0; sc[lane + 32] = e1;
                    if (lane == 0) { g_attM[ab * 2 + half] = m; g_attS[ab * 2 + half] = ssum; }
                }
                __syncthreads();
                {
                    int d = tid;
                    float acc = 0.f;
                    #pragma unroll 8
                    for (int s_loc = 0; s_loc < 64; s_loc++)
                        acc += sc[s_loc] * g_h[(((size_t)(half * 64 + s_loc)) * BB + ab) * DHH + d];
                    g_ctxP[((size_t)half * DHH + d) * 64 + ab] = acc;
                }
                __syncthreads();
            }
            ull acc[4][4] = {};
            wres_rt<8>(g_hdT, WkA, Asm, w, ntile, btile, kl, b8, acc);
            gsync2(blk, ++gen);
            // ===== phase B: flash-merge + ctx-half GEMM + combine + cell =====
            if (tid < 64) {
                float m0 = g_attM[tid * 2], m1 = g_attM[tid * 2 + 1];
                float M = fmaxf(m0, m1);
                float e0 = __expf(m0 - M), e1 = __expf(m1 - M);
                float den = g_attS[tid * 2] * e0 + g_attS[tid * 2 + 1] * e1;
                c0sm[tid] = e0 / den;
                c1sm[tid] = e1 / den;
            }
            __syncthreads();
            float4 c0a = *(const float4*)&c0sm[b8];
            float4 c0b = *(const float4*)&c0sm[b8 + 4];
            float4 c1a = *(const float4*)&c1sm[b8];
            float4 c1b = *(const float4*)&c1sm[b8 + 4];
            wres_rtm<8>(g_ctxP, g_ctxP + DHH * 64, c0a, c1a, c0b, c1b,
                        WkB, Asm, w, ntile, btile, kl, b8, acc);
            float2 s = kseg_combine(Csm, acc, w, ntile, btile, tid);
            {
                int n = tid >> 5, bp = tid & 31;
                const float* pr = pre + ((size_t)t * GD + blk * 16 + n) * 64;
                float2 p2 = *(const float2*)&pr[2 * bp];
                *(float2*)&gsm[n][2 * bp] = make_float2(s.x + p2.x + ohn, s.y + p2.y + ohn);
            }
            __syncthreads();
            if (tid < 256) {
                float gi = gsm[uu][bc], gf = gsm[4 + uu][bc], gg = gsm[8 + uu][bc], go = gsm[12 + uu][bc];
                int u = blk * 4 + uu;
                size_t ci = (size_t)u * BB + bc;
                float c = g_cdT[ci];
                c = sigf(gf) * c + sigf(gi) * tanhf(gg);
                float hn = sigf(go) * tanhf(c);
                g_cdT[ci] = c;
                g_hdT[ci] = hn;
                g_hd[(size_t)bc * DHH + u] = hn;
                g_dout[(((size_t)lvl * SS + t) * BB + bc) * DHH + u] = hn;
            }
            gsync2(blk, ++gen);
        }
    }
}

// ---------------- output projection ----------------
__global__ void out_proj(const float* __restrict__ W2, const float* __restrict__ b2,
                         float* __restrict__ out) {
    int m = blockIdx.x;
    int lane = threadIdx.x;
    const float* drow = g_dout + (size_t)m * DHH;
    float acc[CC] = {};
    for (int k = lane; k < DHH; k += 32) {
        float d = drow[k];
        #pragma unroll
        for (int c = 0; c < CC; c++) acc[c] += d * W2[c * DHH + k];
    }
    #pragma unroll
    for (int c = 0; c < CC; c++) {
        float v = acc[c];
        #pragma unroll
        for (int off = 16; off; off >>= 1) v += __shfl_xor_sync(0xffffffffu, v, off);
        if (lane == 0) out[(size_t)m * CC + c] = v + b2[c];
    }
}

// ---------------- host ----------------
extern "C" void kernel_launch(void* const* d_in, const int* in_sizes, int n_in,
                              void* d_out, int out_size) {
    const int*   seqs  = (const int*)d_in[0];
    const float* emb   = (const float*)d_in[2];
    const float* Wih_f = (const float*)d_in[3];
    const float* Whh_f = (const float*)d_in[4];
    const float* bih_f = (const float*)d_in[5];
    const float* bhh_f = (const float*)d_in[6];
    const float* Wih_b = (const float*)d_in[7];
    const float* Whh_b = (const float*)d_in[8];
    const float* bih_b = (const float*)d_in[9];
    const float* bhh_b = (const float*)d_in[10];
    const float* Wl    = (const float*)d_in[11];
    const float* Wih_d = (const float*)d_in[12];
    const float* Whh_d = (const float*)d_in[13];
    const float* bih_d = (const float*)d_in[14];
    const float* bhh_d = (const float*)d_in[15];
    const float* W2    = (const float*)d_in[16];
    const float* b2    = (const float*)d_in[17];
    float* out = (float*)d_out;

    cudaFuncSetAttribute(enc_persist, cudaFuncAttributeMaxDynamicSharedMemorySize, SMEM_ENC);
    cudaFuncSetAttribute(dec_persist, cudaFuncAttributeMaxDynamicSharedMemorySize, SMEM_DEC);

    // 0: prep (embed + permute + zero)
    k_prep<<<(PREP_TOTAL + 255) / 256, 256>>>(seqs, emb, Whh_f, Whh_b, Wih_f, Wih_b,
                                              bih_f, bhh_f, bih_b, bhh_b,
                                              Wih_d, Whh_d, bih_d, bhh_d);
    // 1: encoder input GEMMs
    k_encg<<<dim3(SS * BB / 64, G4H / 64, 2), 256>>>();
    // 2: encoder recurrence + fused pre0/wh tail
    enc_persist<<<NBE, TPB, SMEM_ENC>>>(Wl);
    // 3: decoder level 0   <-- ncu capture target
    dec_persist<<<NBD, TPB, SMEM_DEC>>>(0, 1);
    // 4: pre1 = pre0 + (dout0 - h)@Wprev
    k_pre1<<<dim3(SS * BB / 64, GD / 64), 256>>>();
    // 5: decoder levels 1-3
    dec_persist<<<NBD, TPB, SMEM_DEC>>>(1, 4);
    // 6: logits
    out_proj<<<LMAXX * SS * BB, 32>>>(W2, b2, out);
}

// round 16
// speedup vs baseline: 1.1760x; 1.0144x over previous
#include <cuda_runtime.h>
#include <math.h>

// ---------------- problem dims ----------------
#define SS    128
#define BB    64
#define EE    512
#define HH    256
#define DHH   512
#define G4H   1024
#define GD    2048
#define LDWD  2052
#define LMAXX 4
#define CC    9

#define NBE   128
#define NBD   128
#define TPB   512

typedef unsigned long long ull;

// gate-locality permutations: block owns all 4 gates of 4 units
__device__ __forceinline__ int enperm(int np) { return (((np >> 2) & 3) << 8) + ((np >> 4) << 2) + (np & 3); }
__device__ __forceinline__ int deperm(int np) { return (((np >> 2) & 3) << 9) + ((np >> 4) << 2) + (np & 3); }

// ---------------- static device scratch ----------------
__device__ float g_x   [SS*BB*EE];
__device__ float g_gxf [SS*BB*G4H];      // TRANSPOSED: [s][np][b]
__device__ float g_gxb [SS*BB*G4H];
__device__ float g_h   [SS*BB*DHH];      // [s][b][d]
__device__ float g_wh  [SS*BB*DHH];      // [s][b][d]
__device__ float g_pre0[SS*BB*GD];       // TRANSPOSED: [t][np][b]
__device__ float g_pre1[SS*BB*GD];
__device__ float g_dout[LMAXX*SS*BB*DHH];
__device__ float g_hencT[2*2*HH*BB];     // [p][dir][u][b]
__device__ float g_cencT[2*HH*BB];
__device__ float g_hd  [BB*DHH];         // [b][u]
__device__ float g_hdT [DHH*BB];         // [u][b]
__device__ float g_cdT [DHH*BB];
__device__ float g_ctxP[2*DHH*BB];       // [half][d][b]
__device__ float g_attM[2*BB];
__device__ float g_attS[2*BB];
__device__ float g_Whhp[2*G4H*HH];       // permuted rows [dir][np][k]
__device__ float g_Wihp[2*G4H*EE];
__device__ float g_bep [2*G4H];
__device__ float g_Wcat[GD*1024];        // permuted rows: [Wih_d[:, :512] | Whh_d]
__device__ float g_Wmid0[GD*1024];       // permuted rows: Wih_d[:,512:1536], h-cols += Wprev
__device__ float g_Wprev[GD*DHH];
__device__ float g_bdp [GD];
__device__ float g_ohcp[LMAXX*GD];

// ---------------- flag-tree grid barrier ----------------
__device__ unsigned g_flags[NBD * 32];
__device__ unsigned g_rel;

__device__ __forceinline__ unsigned bar_base() {
    unsigned v;
    asm volatile("ld.global.u32 %0, [%1];" : "=r"(v) : "l"(&g_rel));
    return v;
}

__device__ __forceinline__ void gsync2(int blk, unsigned gen) {
    __syncthreads();
    if (threadIdx.x == 0)
        asm volatile("st.release.gpu.u32 [%0], %1;" :: "l"(&g_flags[blk * 32]), "r"(gen) : "memory");
    if (blk == 0) {
        if (threadIdx.x < NBD) {
            unsigned v;
            while (true) {
                asm volatile("ld.acquire.gpu.u32 %0, [%1];" : "=r"(v) : "l"(&g_flags[threadIdx.x * 32]) : "memory");
                if ((int)(v - gen) >= 0) break;
                __nanosleep(64);
            }
        }
        __syncthreads();
        if (threadIdx.x == 0)
            asm volatile("st.release.gpu.u32 [%0], %1;" :: "l"(&g_rel), "r"(gen) : "memory");
    } else if (threadIdx.x == 0) {
        unsigned v;
        while (true) {
            asm volatile("ld.acquire.gpu.u32 %0, [%1];" : "=r"(v) : "l"(&g_rel) : "memory");
            if ((int)(v - gen) >= 0) break;
            __nanosleep(64);
        }
    }
    __syncthreads();
}

__device__ __forceinline__ float sigf(float x) { return 1.0f / (1.0f + __expf(-x)); }

__device__ __forceinline__ ull fma2(ull a, ull b, ull c) {
    ull d;
    asm("fma.rn.f32x2 %0, %1, %2, %3;" : "=l"(d) : "l"(a), "l"(b), "l"(c));
    return d;
}
__device__ __forceinline__ float2 unpack2(ull v) {
    float2 r;
    asm("mov.b64 {%0, %1}, %2;" : "=f"(r.x), "=f"(r.y) : "l"(v));
    return r;
}
__device__ __forceinline__ ull splat2(float v) {
    ull r;
    asm("mov.b64 %0, {%1, %1};" : "=l"(r) : "f"(v));
    return r;
}

// ---------------- prep (includes embed) ----------------
#define EMB_TOTAL (SS*BB*EE)
#define Z_TOTAL 196608
#define PREP_TOTAL (EMB_TOTAL + Z_TOTAL + 524288 + 1048576 + 2048 + 2097152 + 2097152 + 1048576 + 2048 + 8192)
__global__ void k_prep(const int* __restrict__ seqs, const float* __restrict__ emb,
                       const float* __restrict__ Whh_f, const float* __restrict__ Whh_b,
                       const float* __restrict__ Wih_f, const float* __restrict__ Wih_b,
                       const float* __restrict__ bih_f, const float* __restrict__ bhh_f,
                       const float* __restrict__ bih_b, const float* __restrict__ bhh_b,
                       const float* __restrict__ Wih_d, const float* __restrict__ Whh_d,
                       const float* __restrict__ bih_d, const float* __restrict__ bhh_d) {
    long long i = (long long)blockIdx.x * 256 + threadIdx.x;
    if (i < EMB_TOTAL) { // embed
        int m = (int)(i >> 9), e = (int)(i & 511);
        int s = m >> 6, b = m & 63;
        g_x[i] = emb[(size_t)seqs[b * SS + s] * EE + e];
        return;
    }
    i -= EMB_TOTAL;
    if (i < Z_TOTAL) {
        if (i < 65536) g_hencT[i] = 0.f;
        else if (i < 98304) g_cencT[i - 65536] = 0.f;
        else if (i < 131072) g_hd[i - 98304] = 0.f;
        else if (i < 163840) g_hdT[i - 131072] = 0.f;
        else g_cdT[i - 163840] = 0.f;
        return;
    }
    i -= Z_TOTAL;
    if (i < 524288) { // Whhp
        int dir = (int)(i >> 18), r = (int)(i & 262143);
        int np = r >> 8, k = r & 255;
        int n = enperm(np);
        g_Whhp[i] = (dir ? Whh_b : Whh_f)[n * HH + k];
        return;
    }
    i -= 524288;
    if (i < 1048576) { // Wihp
        int dir = (int)(i >> 19), r = (int)(i & 524287);
        int np = r >> 9, k = r & 511;
        int n = enperm(np);
        g_Wihp[i] = (dir ? Wih_b : Wih_f)[n * EE + k];
        return;
    }
    i -= 1048576;
    if (i < 2048) { // encoder bias
        int dir = (int)(i >> 10), np = (int)(i & 1023);
        int n = enperm(np);
        g_bep[i] = dir ? (bih_b[n] + bhh_b[n]) : (bih_f[n] + bhh_f[n]);
        return;
    }
    i -= 2048;
    if (i < 2097152) { // Wcat
        int np = (int)(i >> 10), k = (int)(i & 1023);
        int n = deperm(np);
        g_Wcat[i] = (k < 512) ? Wih_d[(size_t)n * LDWD + k] : Whh_d[(size_t)n * DHH + (k - 512)];
        return;
    }
    i -= 2097152;
    if (i < 2097152) { // Wmid0
        int np = (int)(i >> 10), k = (int)(i & 1023);
        int n = deperm(np);
        float v = Wih_d[(size_t)n * LDWD + 512 + k];
        if (k < 512) v += Wih_d[(size_t)n * LDWD + 1536 + k];
        g_Wmid0[i] = v;
        return;
    }
    i -= 2097152;
    if (i < 1048576) { // Wprev
        int np = (int)(i >> 9), k = (int)(i & 511);
        int n = deperm(np);
        g_Wprev[i] = Wih_d[(size_t)n * LDWD + 1536 + k];
        return;
    }
    i -= 1048576;
    if (i < 2048) { // decoder bias
        int n = deperm((int)i);
        g_bdp[i] = bih_d[n] + bhh_d[n];
        return;
    }
    i -= 2048;
    if (i < 8192) { // one-hot columns
        int lvl = (int)(i >> 11), np = (int)(i & 2047);
        int n = deperm(np);
        g_ohcp[i] = Wih_d[(size_t)n * LDWD + GD + lvl];
        return;
    }
}

// ---------------- precompute GEMM cores ----------------
// 256-thread version with static smem (k_encg, k_pre1)
__device__ __forceinline__ void gemm_body(float (*As)[68], float (*Ws)[68], int tid,
                        const float* __restrict__ A, int lda,
                        const float* __restrict__ A2, const float* __restrict__ Asub,
                        const float* __restrict__ W, int ldw,
                        float* __restrict__ C, int N, int K,
                        const float* __restrict__ add, const float* __restrict__ bias,
                        int tpose, int m0, int n0, int barid) {
    int tm = (tid >> 4) << 2, tn = (tid & 15) << 2;
    float acc[4][4] = {};
    for (int k0 = 0; k0 < K; k0 += 16) {
        const float* Asrc = A;
        int kk0 = k0;
        bool second = (A2 && k0 >= 512);
        if (second) { Asrc = A2; kk0 = k0 - 512; }
        #pragma unroll
        for (int i = tid; i < 1024; i += 256) {
            int r = i >> 4, k = i & 15;
            float v = Asrc[(size_t)(m0 + r) * lda + kk0 + k];
            if (Asub && !second) v -= Asub[(size_t)(m0 + r) * lda + kk0 + k];
            As[k][r] = v;
            Ws[k][r] = W[(size_t)(n0 + r) * ldw + k0 + k];
        }
        asm volatile("bar.sync %0, 256;" :: "r"(barid) : "memory");
        #pragma unroll
        for (int k = 0; k < 16; k++) {
            float4 a4 = *(const float4*)&As[k][tm];
            float4 w4 = *(const float4*)&Ws[k][tn];
            acc[0][0] += a4.x * w4.x; acc[0][1] += a4.x * w4.y; acc[0][2] += a4.x * w4.z; acc[0][3] += a4.x * w4.w;
            acc[1][0] += a4.y * w4.x; acc[1][1] += a4.y * w4.y; acc[1][2] += a4.y * w4.z; acc[1][3] += a4.y * w4.w;
            acc[2][0] += a4.z * w4.x; acc[2][1] += a4.z * w4.y; acc[2][2] += a4.z * w4.z; acc[2][3] += a4.z * w4.w;
            acc[3][0] += a4.w * w4.x; acc[3][1] += a4.w * w4.y; acc[3][2] += a4.w * w4.z; acc[3][3] += a4.w * w4.w;
        }
        asm volatile("bar.sync %0, 256;" :: "r"(barid) : "memory");
    }
    #pragma unroll
    for (int i = 0; i < 4; i++)
        #pragma unroll
        for (int j = 0; j < 4; j++) {
            int m = m0 + tm + i, n = n0 + tn + j;
            float v = acc[i][j];
            if (bias) v += bias[n];
            if (tpose) {
                size_t idx = ((size_t)(m >> 6) * N + n) * 64 + (m & 63);
                if (add) v += add[idx];
                C[idx] = v;
            } else {
                size_t idx = (size_t)m * N + n;
                if (add) v += add[idx];
                C[idx] = v;
            }
        }
}

__global__ void __launch_bounds__(256) k_encg() {
    __shared__ __align__(16) float As[16][68];
    __shared__ __align__(16) float Ws[16][68];
    int z = blockIdx.z;
    gemm_body(As, Ws, threadIdx.x, g_x, EE, nullptr, nullptr,
              g_Wihp + (size_t)z * G4H * EE, EE,
              z ? g_gxb : g_gxf, G4H, EE,
              nullptr, g_bep + z * G4H, 1,
              blockIdx.x * 64, blockIdx.y * 64, 0);
}

__global__ void __launch_bounds__(256) k_pre1() {
    __shared__ __align__(16) float As[16][68];
    __shared__ __align__(16) float Ws[16][68];
    gemm_body(As, Ws, threadIdx.x, g_dout, DHH, nullptr, g_h, g_Wprev, DHH, g_pre1, GD, DHH,
              g_pre0, nullptr, 1, blockIdx.x * 64, blockIdx.y * 64, 0);
}

// ---------------- register-tiled W-resident GEMM ----------------
// Warp w = kseg; lane: ntile=lane>>3 (4 n per tile), btile=lane&7 (4 b-pairs per tile).
// Per chunk (64 staged k), warp handles k = c*64 + w*4 .. +3. acc[4n][4bp] f32x2.
template<int CHUNKS>
__device__ __forceinline__ void wres_rt(const float* __restrict__ AT,
                                        const float* __restrict__ Wk,
                                        float (*Asm)[64],
                                        int w, int ntile, int btile, int kl, int b8,
                                        ull acc[4][4]) {
    float4 pf0 = *(const float4*)&AT[kl * 64 + b8];
    float4 pf1 = *(const float4*)&AT[kl * 64 + b8 + 4];
    for (int c = 0; c < CHUNKS; c++) {
        __syncthreads();
        *(float4*)&Asm[kl][b8]     = pf0;
        *(float4*)&Asm[kl][b8 + 4] = pf1;
        __syncthreads();
        if (c < CHUNKS - 1) {
            const float* src = AT + (c + 1) * 4096;
            pf0 = *(const float4*)&src[kl * 64 + b8];
            pf1 = *(const float4*)&src[kl * 64 + b8 + 4];
        }
        const float* wrow = Wk + (c * 64 + w * 4) * 16 + ntile * 4;
        #pragma unroll
        for (int kk = 0; kk < 4; kk++) {
            float4 wv = *(const float4*)(wrow + kk * 16);
            ull w0 = splat2(wv.x), w1 = splat2(wv.y), w2 = splat2(wv.z), w3 = splat2(wv.w);
            const ull* ap = (const ull*)&Asm[w * 4 + kk][btile * 8];
            ull a0 = ap[0], a1 = ap[1], a2 = ap[2], a3 = ap[3];
            acc[0][0] = fma2(a0, w0, acc[0][0]); acc[0][1] = fma2(a1, w0, acc[0][1]);
            acc[0][2] = fma2(a2, w0, acc[0][2]); acc[0][3] = fma2(a3, w0, acc[0][3]);
            acc[1][0] = fma2(a0, w1, acc[1][0]); acc[1][1] = fma2(a1, w1, acc[1][1]);
            acc[1][2] = fma2(a2, w1, acc[1][2]); acc[1][3] = fma2(a3, w1, acc[1][3]);
            acc[2][0] = fma2(a0, w2, acc[2][0]); acc[2][1] = fma2(a1, w2, acc[2][1]);
            acc[2][2] = fma2(a2, w2, acc[2][2]); acc[2][3] = fma2(a3, w2, acc[2][3]);
            acc[3][0] = fma2(a0, w3, acc[3][0]); acc[3][1] = fma2(a1, w3, acc[3][1]);
            acc[3][2] = fma2(a2, w3, acc[3][2]); acc[3][3] = fma2(a3, w3, acc[3][3]);
        }
    }
}

// merged-fill variant (flash-softmax ctx merge)
template<int CHUNKS>
__device__ __forceinline__ void wres_rtm(const float* __restrict__ P0,
                                         const float* __restrict__ P1,
                                         float4 c0a, float4 c1a, float4 c0b, float4 c1b,
                                         const float* __restrict__ Wk,
                                         float (*Asm)[64],
                                         int w, int ntile, int btile, int kl, int b8,
                                         ull acc[4][4]) {
    #define MLD(off, c0, c1) ({ float4 x0 = *(const float4*)&P0[off]; \
                        float4 x1 = *(const float4*)&P1[off]; \
                        float4 r; \
                        r.x = x0.x * c0.x + x1.x * c1.x; \
                        r.y = x0.y * c0.y + x1.y * c1.y; \
                        r.z = x0.z * c0.z + x1.z * c1.z; \
                        r.w = x0.w * c0.w + x1.w * c1.w; r; })
    float4 pf0 = MLD(kl * 64 + b8, c0a, c1a);
    float4 pf1 = MLD(kl * 64 + b8 + 4, c0b, c1b);
    for (int c = 0; c < CHUNKS; c++) {
        __syncthreads();
        *(float4*)&Asm[kl][b8]     = pf0;
        *(float4*)&Asm[kl][b8 + 4] = pf1;
        __syncthreads();
        if (c < CHUNKS - 1) {
            int base = (c + 1) * 4096;
            pf0 = MLD(base + kl * 64 + b8, c0a, c1a);
            pf1 = MLD(base + kl * 64 + b8 + 4, c0b, c1b);
        }
        const float* wrow = Wk + (c * 64 + w * 4) * 16 + ntile * 4;
        #pragma unroll
        for (int kk = 0; kk < 4; kk++) {
            float4 wv = *(const float4*)(wrow + kk * 16);
            ull w0 = splat2(wv.x), w1 = splat2(wv.y), w2 = splat2(wv.z), w3 = splat2(wv.w);
            const ull* ap = (const ull*)&Asm[w * 4 + kk][btile * 8];
            ull a0 = ap[0], a1 = ap[1], a2 = ap[2], a3 = ap[3];
            acc[0][0] = fma2(a0, w0, acc[0][0]); acc[0][1] = fma2(a1, w0, acc[0][1]);
            acc[0][2] = fma2(a2, w0, acc[0][2]); acc[0][3] = fma2(a3, w0, acc[0][3]);
            acc[1][0] = fma2(a0, w1, acc[1][0]); acc[1][1] = fma2(a1, w1, acc[1][1]);
            acc[1][2] = fma2(a2, w1, acc[1][2]); acc[1][3] = fma2(a3, w1, acc[1][3]);
            acc[2][0] = fma2(a0, w2, acc[2][0]); acc[2][1] = fma2(a1, w2, acc[2][1]);
            acc[2][2] = fma2(a2, w2, acc[2][2]); acc[2][3] = fma2(a3, w2, acc[2][3]);
            acc[3][0] = fma2(a0, w3, acc[3][0]); acc[3][1] = fma2(a1, w3, acc[3][1]);
            acc[3][2] = fma2(a2, w3, acc[3][2]); acc[3][3] = fma2(a3, w3, acc[3][3]);
        }
    }
    #undef MLD
}

// stage per-warp accs into Csm and reduce over 16 warps; returns float2 for (n=tid>>5, bp=tid&31)
__device__ __forceinline__ float2 kseg_combine(float* Csm, ull acc[4][4],
                                               int w, int ntile, int btile, int tid) {
    __syncthreads();   // all compute done; Asm region reusable
    ull* Cu = (ull*)Csm;
    #pragma unroll
    for (int i = 0; i < 4; i++)
        #pragma unroll
        for (int j = 0; j < 4; j++)
            Cu[w * 512 + (ntile * 4 + i) * 32 + (btile * 4 + j)] = acc[i][j];
    __syncthreads();
    float2 s = make_float2(0.f, 0.f);
    #pragma unroll
    for (int ww = 0; ww < 16; ww++) {
        float2 v = unpack2(Cu[ww * 512 + tid]);
        s.x += v.x; s.y += v.y;
    }
    return s;
}

// ---------------- persistent encoder (+ fused pre0/wh tail) ----------------
#define SMEM_ENC ((HH*16 + 16*1024) * 4)   // Wsm 16KB + Csm 64KB (Asm overlays Csm front)
__global__ void __launch_bounds__(TPB, 1) enc_persist(const float* __restrict__ Wl) {
    extern __shared__ __align__(16) float dyn[];
    float* Wsm = dyn;                        // [256][16]
    float* Csm = dyn + HH * 16;              // 16K floats
    float (*Asm)[64] = (float(*)[64])Csm;    // front 16KB
    __shared__ float gsm[16][64];
    int blk = blockIdx.x, tid = threadIdx.x;
    int dir = blk >> 6, ub = blk & 63;
    for (int i = tid; i < 16 * HH; i += TPB) {
        int r = i >> 8, k = i & 255;
        Wsm[k * 16 + r] = g_Whhp[((size_t)dir * G4H + ub * 16 + r) * HH + k];
    }
    __syncthreads();
    int lane = tid & 31, w = tid >> 5;
    int ntile = lane >> 3, btile = lane & 7;
    int kl = tid >> 3, b8 = (tid & 7) << 3;
    int uu = tid >> 6, bc = tid & 63;        // cell (tid<256)
    unsigned gen = bar_base();
    int p = 0;
    for (int t = 0; t < SS; t++) {
        const float* AT = g_hencT + ((size_t)p * 2 + dir) * HH * BB;
        ull acc[4][4] = {};
        wres_rt<4>(AT, Wsm, Asm, w, ntile, btile, kl, b8, acc);
        float2 s = kseg_combine(Csm, acc, w, ntile, btile, tid);
        int s0 = dir ? (SS - 1 - t) : t;
        {
            int n = tid >> 5, bp = tid & 31;
            const float* gx = (dir ? g_gxb : g_gxf) + ((size_t)s0 * G4H + ub * 16 + n) * 64;
            float2 g2 = *(const float2*)&gx[2 * bp];
            *(float2*)&gsm[n][2 * bp] = make_float2(s.x + g2.x, s.y + g2.y);
        }
        __syncthreads();
        if (tid < 256) {
            float gi = gsm[uu][bc], gf = gsm[4 + uu][bc], gg = gsm[8 + uu][bc], go = gsm[12 + uu][bc];
            int u = ub * 4 + uu;
            size_t ci = ((size_t)dir * HH + u) * BB + bc;
            float c = g_cencT[ci];
            c = sigf(gf) * c + sigf(gi) * tanhf(gg);
            float hn = sigf(go) * tanhf(c);
            g_cencT[ci] = c;
            g_hencT[((size_t)(p ^ 1) * 2 + dir) * HH * BB + (size_t)u * BB + bc] = hn;
            g_h[((size_t)s0 * BB + bc) * DHH + dir * HH + u] = hn;
        }
        p ^= 1;
        gsync2(blk, ++gen);
    }
    // ---- fused tail: pre0 = [h|x]@Wmid0+bd (4096 tiles) and wh = h@Wl (1024 tiles) ----
    {
        int hh = tid >> 8;                 // half 0/1
        int t256 = tid & 255;
        float (*As)[68] = (float(*)[68])(dyn + hh * 2432);
        float (*Ws)[68] = (float(*)[68])(dyn + hh * 2432 + 1120);
        for (int i = 0; i < 20; i++) {
            int T = blk * 40 + hh * 20 + i;
            if (T < 4096) {
                gemm_body(As, Ws, t256, g_h, DHH, g_x, nullptr, g_Wmid0, 1024,
                          g_pre0, GD, 1024, nullptr, g_bdp, 1,
                          (T >> 5) * 64, (T & 31) * 64, 1 + hh);
            } else {
                int t2 = T - 4096;
                gemm_body(As, Ws, t256, g_h, DHH, nullptr, nullptr, Wl, DHH,
                          g_wh, DHH, DHH, nullptr, nullptr, 0,
                          (t2 >> 3) * 64, (t2 & 7) * 64, 1 + hh);
            }
        }
    }
}

// ---------------- persistent decoder ----------------
#define SMEM_DEC ((1024*16 + 16*1024) * 4)  // Wsm 64KB + Csm 64KB = 128KB
__global__ void __launch_bounds__(TPB, 1) dec_persist(int l0, int l1) {
    extern __shared__ __align__(16) float dyn[];
    float* Wsm = dyn;                        // [1024][16]
    float* Csm = dyn + 1024 * 16;
    float (*Asm)[64] = (float(*)[64])Csm;
    __shared__ float gsm[16][64];
    __shared__ __align__(16) float hd_s[DHH];
    __shared__ float sc[64];
    __shared__ __align__(16) float c0sm[64], c1sm[64];
    int blk = blockIdx.x, tid = threadIdx.x;
    int half = blk & 1, ab = blk >> 1;
    for (int i = tid; i < 16 * 1024; i += TPB) {
        int r = i >> 10, k = i & 1023;
        Wsm[k * 16 + r] = g_Wcat[((size_t)blk * 16 + r) * 1024 + k];
    }
    __syncthreads();
    int lane = tid & 31, w = tid >> 5;
    int ntile = lane >> 3, btile = lane & 7;
    int kl = tid >> 3, b8 = (tid & 7) << 3;
    int uu = tid >> 6, bc = tid & 63;
    const float* WkA = Wsm + 512 * 16;       // hd half (k 512..1023)
    const float* WkB = Wsm;                  // ctx half (k 0..511)
    unsigned gen = bar_base();
    for (int lvl = l0; lvl < l1; lvl++) {
        const float* pre = (lvl == 0) ? g_pre0 : g_pre1;
        float ohn = g_ohcp[lvl * GD + blk * 16 + (tid >> 5)];
        for (int t = 0; t < SS; t++) {
            // ===== phase A: attention half, then hd-half GEMM =====
            {
                for (int i = tid; i < DHH; i += TPB) hd_s[i] = g_hd[ab * DHH + i];
                __syncthreads();
                for (int it = 0; it < 4; it++) {
                    int s_loc = w * 4 + it;
                    int s = half * 64 + s_loc;
                    const float4* w4 = (const float4*)(g_wh + ((size_t)s * BB + ab) * DHH);
                    const float4* h4 = (const float4*)hd_s;
                    float sum = 0.f;
                    #pragma unroll
                    for (int qq = 0; qq < 4; qq++) {
                        float4 a = w4[lane * 4 + qq];
                        float4 c = h4[lane * 4 + qq];
                        sum += a.x * c.x + a.y * c.y + a.z * c.z + a.w * c.w;
                    }
                    #pragma unroll
                    for (int off = 16; off; off >>= 1) sum += __shfl_xor_sync(0xffffffffu, sum, off);
                    if (lane == 0) sc[s_loc] = sum;
                }
                __syncthreads();
                if (w == 0) {   // single-warp softmax over 64 scores
                    float v0 = sc[lane], v1 = sc[lane + 32];
                    float m = fmaxf(v0, v1);
                    #pragma unroll
                    for (int off = 16; off; off >>= 1) m = fmaxf(m, __shfl_xor_sync(0xffffffffu, m, off));
                    float e0 = __expf(v0 - m), e1 = __expf(v1 - m);
                    float ssum = e0 + e1;
                    #pragma unroll
                    for (int off = 16; off; off >>= 1) ssum += __shfl_xor_sync(0xffffffffu, ssum, off);
                    sc[lane] = e0; sc[lane + 32] = e1;
                    if (lane == 0) { g_attM[ab * 2 + half] = m; g_attS[ab * 2 + half] = ssum; }
                }
                __syncthreads();
                {
                    int d = tid;
                    float acc = 0.f;
                    #pragma unroll 8
                    for (int s_loc = 0; s_loc < 64; s_loc++)
                        acc += sc[s_loc] * g_h[(((size_t)(half * 64 + s_loc)) * BB + ab) * DHH + d];
                    g_ctxP[((size_t)half * DHH + d) * 64 + ab] = acc;
                }
                __syncthreads();
            }
            ull acc[4][4] = {};
            wres_rt<8>(g_hdT, WkA, Asm, w, ntile, btile, kl, b8, acc);
            gsync2(blk, ++gen);
            // ===== phase B: flash-merge + ctx-half GEMM + combine + cell =====
            if (tid < 64) {
                float m0 = g_attM[tid * 2], m1 = g_attM[tid * 2 + 1];
                float M = fmaxf(m0, m1);
                float e0 = __expf(m0 - M), e1 = __expf(m1 - M);
                float den = g_attS[tid * 2] * e0 + g_attS[tid * 2 + 1] * e1;
                c0sm[tid] = e0 / den;
                c1sm[tid] = e1 / den;
            }
            __syncthreads();
            float4 c0a = *(const float4*)&c0sm[b8];
            float4 c0b = *(const float4*)&c0sm[b8 + 4];
            float4 c1a = *(const float4*)&c1sm[b8];
            float4 c1b = *(const float4*)&c1sm[b8 + 4];
            wres_rtm<8>(g_ctxP, g_ctxP + DHH * 64, c0a, c1a, c0b, c1b,
                        WkB, Asm, w, ntile, btile, kl, b8, acc);
            float2 s = kseg_combine(Csm, acc, w, ntile, btile, tid);
            {
                int n = tid >> 5, bp = tid & 31;
                const float* pr = pre + ((size_t)t * GD + blk * 16 + n) * 64;
                float2 p2 = *(const float2*)&pr[2 * bp];
                *(float2*)&gsm[n][2 * bp] = make_float2(s.x + p2.x + ohn, s.y + p2.y + ohn);
            }
            __syncthreads();
            if (tid < 256) {
                float gi = gsm[uu][bc], gf = gsm[4 + uu][bc], gg = gsm[8 + uu][bc], go = gsm[12 + uu][bc];
                int u = blk * 4 + uu;
                size_t ci = (size_t)u * BB + bc;
                float c = g_cdT[ci];
                c = sigf(gf) * c + sigf(gi) * tanhf(gg);
                float hn = sigf(go) * tanhf(c);
                g_cdT[ci] = c;
                g_hdT[ci] = hn;
                g_hd[(size_t)bc * DHH + u] = hn;
                g_dout[(((size_t)lvl * SS + t) * BB + bc) * DHH + u] = hn;
            }
            gsync2(blk, ++gen);
        }
    }
}

// ---------------- output projection ----------------
__global__ void out_proj(const float* __restrict__ W2, const float* __restrict__ b2,
                         float* __restrict__ out) {
    int m = blockIdx.x;
    int lane = threadIdx.x;
    const float* drow = g_dout + (size_t)m * DHH;
    float acc[CC] = {};
    for (int k = lane; k < DHH; k += 32) {
        float d = drow[k];
        #pragma unroll
        for (int c = 0; c < CC; c++) acc[c] += d * W2[c * DHH + k];
    }
    #pragma unroll
    for (int c = 0; c < CC; c++) {
        float v = acc[c];
        #pragma unroll
        for (int off = 16; off; off >>= 1) v += __shfl_xor_sync(0xffffffffu, v, off);
        if (lane == 0) out[(size_t)m * CC + c] = v + b2[c];
    }
}

// ---------------- host ----------------
extern "C" void kernel_launch(void* const* d_in, const int* in_sizes, int n_in,
                              void* d_out, int out_size) {
    const int*   seqs  = (const int*)d_in[0];
    const float* emb   = (const float*)d_in[2];
    const float* Wih_f = (const float*)d_in[3];
    const float* Whh_f = (const float*)d_in[4];
    const float* bih_f = (const float*)d_in[5];
    const float* bhh_f = (const float*)d_in[6];
    const float* Wih_b = (const float*)d_in[7];
    const float* Whh_b = (const float*)d_in[8];
    const float* bih_b = (const float*)d_in[9];
    const float* bhh_b = (const float*)d_in[10];
    const float* Wl    = (const float*)d_in[11];
    const float* Wih_d = (const float*)d_in[12];
    const float* Whh_d = (const float*)d_in[13];
    const float* bih_d = (const float*)d_in[14];
    const float* bhh_d = (const float*)d_in[15];
    const float* W2    = (const float*)d_in[16];
    const float* b2    = (const float*)d_in[17];
    float* out = (float*)d_out;

    cudaFuncSetAttribute(enc_persist, cudaFuncAttributeMaxDynamicSharedMemorySize, SMEM_ENC);
    cudaFuncSetAttribute(dec_persist, cudaFuncAttributeMaxDynamicSharedMemorySize, SMEM_DEC);

    // 0: prep (embed + permute + zero)
    k_prep<<<(PREP_TOTAL + 255) / 256, 256>>>(seqs, emb, Whh_f, Whh_b, Wih_f, Wih_b,
                                              bih_f, bhh_f, bih_b, bhh_b,
                                              Wih_d, Whh_d, bih_d, bhh_d);
    // 1: encoder input GEMMs
    k_encg<<<dim3(SS * BB / 64, G4H / 64, 2), 256>>>();
    // 2: encoder recurrence + fused pre0/wh tail
    enc_persist<<<NBE, TPB, SMEM_ENC>>>(Wl);
    // 3: decoder level 0   <-- ncu capture target
    dec_persist<<<NBD, TPB, SMEM_DEC>>>(0, 1);
    // 4: pre1 = pre0 + (dout0 - h)@Wprev
    k_pre1<<<dim3(SS * BB / 64, GD / 64), 256>>>();
    // 5: decoder levels 1-3
    dec_persist<<<NBD, TPB, SMEM_DEC>>>(1, 4);
    // 6: logits
    out_proj<<<LMAXX * SS * BB, 32>>>(W2, b2, out);
}

// round 17
// speedup vs baseline: 1.1766x; 1.0005x over previous
#include <cuda_runtime.h>
#include <math.h>

// ---------------- problem dims ----------------
#define SS    128
#define BB    64
#define EE    512
#define HH    256
#define DHH   512
#define G4H   1024
#define GD    2048
#define LDWD  2052
#define LMAXX 4
#define CC    9

#define NBE   128
#define NBD   128
#define TPB   512

typedef unsigned long long ull;

// gate-locality permutations: block owns all 4 gates of 4 units
__device__ __forceinline__ int enperm(int np) { return (((np >> 2) & 3) << 8) + ((np >> 4) << 2) + (np & 3); }
__device__ __forceinline__ int deperm(int np) { return (((np >> 2) & 3) << 9) + ((np >> 4) << 2) + (np & 3); }

// ---------------- static device scratch ----------------
__device__ float g_x   [SS*BB*EE];
__device__ float g_gxf [SS*BB*G4H];      // TRANSPOSED: [s][np][b]
__device__ float g_gxb [SS*BB*G4H];
__device__ float g_h   [SS*BB*DHH];      // [s][b][d]
__device__ float g_wh  [SS*BB*DHH];      // [s][b][d]
__device__ float g_pre0[SS*BB*GD];       // TRANSPOSED: [t][np][b]
__device__ float g_pre1[SS*BB*GD];
__device__ float g_dout[LMAXX*SS*BB*DHH];
__device__ float g_hencT[2*2*HH*BB];     // [p][dir][u][b]
__device__ float g_cencT[2*HH*BB];
__device__ float g_hd  [BB*DHH];         // [b][u]
__device__ float g_hdT [DHH*BB];         // [u][b]
__device__ float g_cdT [DHH*BB];
__device__ float g_ctxP[2*DHH*BB];       // [half][d][b]
__device__ float g_attM[2*BB];
__device__ float g_attS[2*BB];
__device__ float g_Whhp[2*G4H*HH];       // permuted rows [dir][np][k]
__device__ float g_Wihp[2*G4H*EE];
__device__ float g_bep [2*G4H];
__device__ float g_Wcat[GD*1024];        // permuted rows: [Wih_d[:, :512] | Whh_d]
__device__ float g_Wmid0[GD*1024];       // permuted rows: Wih_d[:,512:1536], h-cols += Wprev
__device__ float g_Wprev[GD*DHH];
__device__ float g_bdp [GD];
__device__ float g_ohcp[LMAXX*GD];

// ---------------- flag-tree grid barrier ----------------
__device__ unsigned g_flags[NBD * 32];
__device__ unsigned g_rel;

__device__ __forceinline__ unsigned bar_base() {
    unsigned v;
    asm volatile("ld.global.u32 %0, [%1];" : "=r"(v) : "l"(&g_rel));
    return v;
}

__device__ __forceinline__ void gsync2(int blk, unsigned gen) {
    __syncthreads();
    if (threadIdx.x == 0)
        asm volatile("st.release.gpu.u32 [%0], %1;" :: "l"(&g_flags[blk * 32]), "r"(gen) : "memory");
    if (blk == 0) {
        if (threadIdx.x < NBD) {
            unsigned v;
            while (true) {
                asm volatile("ld.acquire.gpu.u32 %0, [%1];" : "=r"(v) : "l"(&g_flags[threadIdx.x * 32]) : "memory");
                if ((int)(v - gen) >= 0) break;
                __nanosleep(64);
            }
        }
        __syncthreads();
        if (threadIdx.x == 0)
            asm volatile("st.release.gpu.u32 [%0], %1;" :: "l"(&g_rel), "r"(gen) : "memory");
    } else if (threadIdx.x == 0) {
        unsigned v;
        while (true) {
            asm volatile("ld.acquire.gpu.u32 %0, [%1];" : "=r"(v) : "l"(&g_rel) : "memory");
            if ((int)(v - gen) >= 0) break;
            __nanosleep(64);
        }
    }
    __syncthreads();
}

__device__ __forceinline__ float sigf(float x) { return 1.0f / (1.0f + __expf(-x)); }

__device__ __forceinline__ ull fma2(ull a, ull b, ull c) {
    ull d;
    asm("fma.rn.f32x2 %0, %1, %2, %3;" : "=l"(d) : "l"(a), "l"(b), "l"(c));
    return d;
}
__device__ __forceinline__ float2 unpack2(ull v) {
    float2 r;
    asm("mov.b64 {%0, %1}, %2;" : "=f"(r.x), "=f"(r.y) : "l"(v));
    return r;
}
__device__ __forceinline__ ull splat2(float v) {
    ull r;
    asm("mov.b64 %0, {%1, %1};" : "=l"(r) : "f"(v));
    return r;
}

// ---------------- prep (includes embed) ----------------
#define EMB_TOTAL (SS*BB*EE)
#define Z_TOTAL 196608
#define PREP_TOTAL (EMB_TOTAL + Z_TOTAL + 524288 + 1048576 + 2048 + 2097152 + 2097152 + 1048576 + 2048 + 8192)
__global__ void k_prep(const int* __restrict__ seqs, const float* __restrict__ emb,
                       const float* __restrict__ Whh_f, const float* __restrict__ Whh_b,
                       const float* __restrict__ Wih_f, const float* __restrict__ Wih_b,
                       const float* __restrict__ bih_f, const float* __restrict__ bhh_f,
                       const float* __restrict__ bih_b, const float* __restrict__ bhh_b,
                       const float* __restrict__ Wih_d, const float* __restrict__ Whh_d,
                       const float* __restrict__ bih_d, const float* __restrict__ bhh_d) {
    long long i = (long long)blockIdx.x * 256 + threadIdx.x;
    if (i < EMB_TOTAL) { // embed
        int m = (int)(i >> 9), e = (int)(i & 511);
        int s = m >> 6, b = m & 63;
        g_x[i] = emb[(size_t)seqs[b * SS + s] * EE + e];
        return;
    }
    i -= EMB_TOTAL;
    if (i < Z_TOTAL) {
        if (i < 65536) g_hencT[i] = 0.f;
        else if (i < 98304) g_cencT[i - 65536] = 0.f;
        else if (i < 131072) g_hd[i - 98304] = 0.f;
        else if (i < 163840) g_hdT[i - 131072] = 0.f;
        else g_cdT[i - 163840] = 0.f;
        return;
    }
    i -= Z_TOTAL;
    if (i < 524288) { // Whhp
        int dir = (int)(i >> 18), r = (int)(i & 262143);
        int np = r >> 8, k = r & 255;
        int n = enperm(np);
        g_Whhp[i] = (dir ? Whh_b : Whh_f)[n * HH + k];
        return;
    }
    i -= 524288;
    if (i < 1048576) { // Wihp
        int dir = (int)(i >> 19), r = (int)(i & 524287);
        int np = r >> 9, k = r & 511;
        int n = enperm(np);
        g_Wihp[i] = (dir ? Wih_b : Wih_f)[n * EE + k];
        return;
    }
    i -= 1048576;
    if (i < 2048) { // encoder bias
        int dir = (int)(i >> 10), np = (int)(i & 1023);
        int n = enperm(np);
        g_bep[i] = dir ? (bih_b[n] + bhh_b[n]) : (bih_f[n] + bhh_f[n]);
        return;
    }
    i -= 2048;
    if (i < 2097152) { // Wcat
        int np = (int)(i >> 10), k = (int)(i & 1023);
        int n = deperm(np);
        g_Wcat[i] = (k < 512) ? Wih_d[(size_t)n * LDWD + k] : Whh_d[(size_t)n * DHH + (k - 512)];
        return;
    }
    i -= 2097152;
    if (i < 2097152) { // Wmid0
        int np = (int)(i >> 10), k = (int)(i & 1023);
        int n = deperm(np);
        float v = Wih_d[(size_t)n * LDWD + 512 + k];
        if (k < 512) v += Wih_d[(size_t)n * LDWD + 1536 + k];
        g_Wmid0[i] = v;
        return;
    }
    i -= 2097152;
    if (i < 1048576) { // Wprev
        int np = (int)(i >> 9), k = (int)(i & 511);
        int n = deperm(np);
        g_Wprev[i] = Wih_d[(size_t)n * LDWD + 1536 + k];
        return;
    }
    i -= 1048576;
    if (i < 2048) { // decoder bias
        int n = deperm((int)i);
        g_bdp[i] = bih_d[n] + bhh_d[n];
        return;
    }
    i -= 2048;
    if (i < 8192) { // one-hot columns
        int lvl = (int)(i >> 11), np = (int)(i & 2047);
        int n = deperm(np);
        g_ohcp[i] = Wih_d[(size_t)n * LDWD + GD + lvl];
        return;
    }
}

// ---------------- precompute GEMM cores ----------------
// 256-thread version with static smem (k_encg, k_pre1)
__device__ __forceinline__ void gemm_body(float (*As)[68], float (*Ws)[68], int tid,
                        const float* __restrict__ A, int lda,
                        const float* __restrict__ A2, const float* __restrict__ Asub,
                        const float* __restrict__ W, int ldw,
                        float* __restrict__ C, int N, int K,
                        const float* __restrict__ add, const float* __restrict__ bias,
                        int tpose, int m0, int n0, int barid) {
    int tm = (tid >> 4) << 2, tn = (tid & 15) << 2;
    float acc[4][4] = {};
    for (int k0 = 0; k0 < K; k0 += 16) {
        const float* Asrc = A;
        int kk0 = k0;
        bool second = (A2 && k0 >= 512);
        if (second) { Asrc = A2; kk0 = k0 - 512; }
        #pragma unroll
        for (int i = tid; i < 1024; i += 256) {
            int r = i >> 4, k = i & 15;
            float v = Asrc[(size_t)(m0 + r) * lda + kk0 + k];
            if (Asub && !second) v -= Asub[(size_t)(m0 + r) * lda + kk0 + k];
            As[k][r] = v;
            Ws[k][r] = W[(size_t)(n0 + r) * ldw + k0 + k];
        }
        asm volatile("bar.sync %0, 256;" :: "r"(barid) : "memory");
        #pragma unroll
        for (int k = 0; k < 16; k++) {
            float4 a4 = *(const float4*)&As[k][tm];
            float4 w4 = *(const float4*)&Ws[k][tn];
            acc[0][0] += a4.x * w4.x; acc[0][1] += a4.x * w4.y; acc[0][2] += a4.x * w4.z; acc[0][3] += a4.x * w4.w;
            acc[1][0] += a4.y * w4.x; acc[1][1] += a4.y * w4.y; acc[1][2] += a4.y * w4.z; acc[1][3] += a4.y * w4.w;
            acc[2][0] += a4.z * w4.x; acc[2][1] += a4.z * w4.y; acc[2][2] += a4.z * w4.z; acc[2][3] += a4.z * w4.w;
            acc[3][0] += a4.w * w4.x; acc[3][1] += a4.w * w4.y; acc[3][2] += a4.w * w4.z; acc[3][3] += a4.w * w4.w;
        }
        asm volatile("bar.sync %0, 256;" :: "r"(barid) : "memory");
    }
    #pragma unroll
    for (int i = 0; i < 4; i++)
        #pragma unroll
        for (int j = 0; j < 4; j++) {
            int m = m0 + tm + i, n = n0 + tn + j;
            float v = acc[i][j];
            if (bias) v += bias[n];
            if (tpose) {
                size_t idx = ((size_t)(m >> 6) * N + n) * 64 + (m & 63);
                if (add) v += add[idx];
                C[idx] = v;
            } else {
                size_t idx = (size_t)m * N + n;
                if (add) v += add[idx];
                C[idx] = v;
            }
        }
}

__global__ void __launch_bounds__(256) k_encg() {
    __shared__ __align__(16) float As[16][68];
    __shared__ __align__(16) float Ws[16][68];
    int z = blockIdx.z;
    gemm_body(As, Ws, threadIdx.x, g_x, EE, nullptr, nullptr,
              g_Wihp + (size_t)z * G4H * EE, EE,
              z ? g_gxb : g_gxf, G4H, EE,
              nullptr, g_bep + z * G4H, 1,
              blockIdx.x * 64, blockIdx.y * 64, 0);
}

__global__ void __launch_bounds__(256) k_pre1() {
    __shared__ __align__(16) float As[16][68];
    __shared__ __align__(16) float Ws[16][68];
    gemm_body(As, Ws, threadIdx.x, g_dout, DHH, nullptr, g_h, g_Wprev, DHH, g_pre1, GD, DHH,
              g_pre0, nullptr, 1, blockIdx.x * 64, blockIdx.y * 64, 0);
}

// ---------------- register-tiled W-resident GEMM ----------------
// Warp w = kseg; lane: ntile=lane>>3 (4 n per tile), btile=lane&7 (4 b-pairs per tile).
// Per chunk (64 staged k), warp handles k = c*64 + w*4 .. +3. acc[4n][4bp] f32x2.
template<int CHUNKS>
__device__ __forceinline__ void wres_rt(const float* __restrict__ AT,
                                        const float* __restrict__ Wk,
                                        float (*Asm)[64],
                                        int w, int ntile, int btile, int kl, int b8,
                                        ull acc[4][4]) {
    float4 pf0 = *(const float4*)&AT[kl * 64 + b8];
    float4 pf1 = *(const float4*)&AT[kl * 64 + b8 + 4];
    for (int c = 0; c < CHUNKS; c++) {
        __syncthreads();
        *(float4*)&Asm[kl][b8]     = pf0;
        *(float4*)&Asm[kl][b8 + 4] = pf1;
        __syncthreads();
        if (c < CHUNKS - 1) {
            const float* src = AT + (c + 1) * 4096;
            pf0 = *(const float4*)&src[kl * 64 + b8];
            pf1 = *(const float4*)&src[kl * 64 + b8 + 4];
        }
        const float* wrow = Wk + (c * 64 + w * 4) * 16 + ntile * 4;
        #pragma unroll
        for (int kk = 0; kk < 4; kk++) {
            float4 wv = *(const float4*)(wrow + kk * 16);
            ull w0 = splat2(wv.x), w1 = splat2(wv.y), w2 = splat2(wv.z), w3 = splat2(wv.w);
            const ull* ap = (const ull*)&Asm[w * 4 + kk][btile * 8];
            ull a0 = ap[0], a1 = ap[1], a2 = ap[2], a3 = ap[3];
            acc[0][0] = fma2(a0, w0, acc[0][0]); acc[0][1] = fma2(a1, w0, acc[0][1]);
            acc[0][2] = fma2(a2, w0, acc[0][2]); acc[0][3] = fma2(a3, w0, acc[0][3]);
            acc[1][0] = fma2(a0, w1, acc[1][0]); acc[1][1] = fma2(a1, w1, acc[1][1]);
            acc[1][2] = fma2(a2, w1, acc[1][2]); acc[1][3] = fma2(a3, w1, acc[1][3]);
            acc[2][0] = fma2(a0, w2, acc[2][0]); acc[2][1] = fma2(a1, w2, acc[2][1]);
            acc[2][2] = fma2(a2, w2, acc[2][2]); acc[2][3] = fma2(a3, w2, acc[2][3]);
            acc[3][0] = fma2(a0, w3, acc[3][0]); acc[3][1] = fma2(a1, w3, acc[3][1]);
            acc[3][2] = fma2(a2, w3, acc[3][2]); acc[3][3] = fma2(a3, w3, acc[3][3]);
        }
    }
}

// merged-fill variant (flash-softmax ctx merge)
template<int CHUNKS>
__device__ __forceinline__ void wres_rtm(const float* __restrict__ P0,
                                         const float* __restrict__ P1,
                                         float4 c0a, float4 c1a, float4 c0b, float4 c1b,
                                         const float* __restrict__ Wk,
                                         float (*Asm)[64],
                                         int w, int ntile, int btile, int kl, int b8,
                                         ull acc[4][4]) {
    #define MLD(off, c0, c1) ({ float4 x0 = *(const float4*)&P0[off]; \
                        float4 x1 = *(const float4*)&P1[off]; \
                        float4 r; \
                        r.x = x0.x * c0.x + x1.x * c1.x; \
                        r.y = x0.y * c0.y + x1.y * c1.y; \
                        r.z = x0.z * c0.z + x1.z * c1.z; \
                        r.w = x0.w * c0.w + x1.w * c1.w; r; })
    float4 pf0 = MLD(kl * 64 + b8, c0a, c1a);
    float4 pf1 = MLD(kl * 64 + b8 + 4, c0b, c1b);
    for (int c = 0; c < CHUNKS; c++) {
        __syncthreads();
        *(float4*)&Asm[kl][b8]     = pf0;
        *(float4*)&Asm[kl][b8 + 4] = pf1;
        __syncthreads();
        if (c < CHUNKS - 1) {
            int base = (c + 1) * 4096;
            pf0 = MLD(base + kl * 64 + b8, c0a, c1a);
            pf1 = MLD(base + kl * 64 + b8 + 4, c0b, c1b);
        }
        const float* wrow = Wk + (c * 64 + w * 4) * 16 + ntile * 4;
        #pragma unroll
        for (int kk = 0; kk < 4; kk++) {
            float4 wv = *(const float4*)(wrow + kk * 16);
            ull w0 = splat2(wv.x), w1 = splat2(wv.y), w2 = splat2(wv.z), w3 = splat2(wv.w);
            const ull* ap = (const ull*)&Asm[w * 4 + kk][btile * 8];
            ull a0 = ap[0], a1 = ap[1], a2 = ap[2], a3 = ap[3];
            acc[0][0] = fma2(a0, w0, acc[0][0]); acc[0][1] = fma2(a1, w0, acc[0][1]);
            acc[0][2] = fma2(a2, w0, acc[0][2]); acc[0][3] = fma2(a3, w0, acc[0][3]);
            acc[1][0] = fma2(a0, w1, acc[1][0]); acc[1][1] = fma2(a1, w1, acc[1][1]);
            acc[1][2] = fma2(a2, w1, acc[1][2]); acc[1][3] = fma2(a3, w1, acc[1][3]);
            acc[2][0] = fma2(a0, w2, acc[2][0]); acc[2][1] = fma2(a1, w2, acc[2][1]);
            acc[2][2] = fma2(a2, w2, acc[2][2]); acc[2][3] = fma2(a3, w2, acc[2][3]);
            acc[3][0] = fma2(a0, w3, acc[3][0]); acc[3][1] = fma2(a1, w3, acc[3][1]);
            acc[3][2] = fma2(a2, w3, acc[3][2]); acc[3][3] = fma2(a3, w3, acc[3][3]);
        }
    }
    #undef MLD
}

// stage per-warp accs into Csm and reduce over 16 warps; returns float2 for (n=tid>>5, bp=tid&31)
__device__ __forceinline__ float2 kseg_combine(float* Csm, ull acc[4][4],
                                               int w, int ntile, int btile, int tid) {
    __syncthreads();   // all compute done; Asm region reusable
    ull* Cu = (ull*)Csm;
    #pragma unroll
    for (int i = 0; i < 4; i++)
        #pragma unroll
        for (int j = 0; j < 4; j++)
            Cu[w * 512 + (ntile * 4 + i) * 32 + (btile * 4 + j)] = acc[i][j];
    __syncthreads();
    float2 s = make_float2(0.f, 0.f);
    #pragma unroll
    for (int ww = 0; ww < 16; ww++) {
        float2 v = unpack2(Cu[ww * 512 + tid]);
        s.x += v.x; s.y += v.y;
    }
    return s;
}

// ---------------- persistent encoder (+ fused pre0/wh tail) ----------------
#define SMEM_ENC ((HH*16 + 16*1024) * 4)   // Wsm 16KB + Csm 64KB (Asm overlays Csm front)
__global__ void __launch_bounds__(TPB, 1) enc_persist(const float* __restrict__ Wl) {
    extern __shared__ __align__(16) float dyn[];
    float* Wsm = dyn;                        // [256][16]
    float* Csm = dyn + HH * 16;              // 16K floats
    float (*Asm)[64] = (float(*)[64])Csm;    // front 16KB
    __shared__ float gsm[16][64];
    int blk = blockIdx.x, tid = threadIdx.x;
    int dir = blk >> 6, ub = blk & 63;
    for (int i = tid; i < 16 * HH; i += TPB) {
        int r = i >> 8, k = i & 255;
        Wsm[k * 16 + r] = g_Whhp[((size_t)dir * G4H + ub * 16 + r) * HH + k];
    }
    __syncthreads();
    int lane = tid & 31, w = tid >> 5;
    int ntile = lane >> 3, btile = lane & 7;
    int kl = tid >> 3, b8 = (tid & 7) << 3;
    int uu = tid >> 6, bc = tid & 63;        // cell (tid<256)
    unsigned gen = bar_base();
    int p = 0;
    for (int t = 0; t < SS; t++) {
        const float* AT = g_hencT + ((size_t)p * 2 + dir) * HH * BB;
        ull acc[4][4] = {};
        wres_rt<4>(AT, Wsm, Asm, w, ntile, btile, kl, b8, acc);
        float2 s = kseg_combine(Csm, acc, w, ntile, btile, tid);
        int s0 = dir ? (SS - 1 - t) : t;
        {
            int n = tid >> 5, bp = tid & 31;
            const float* gx = (dir ? g_gxb : g_gxf) + ((size_t)s0 * G4H + ub * 16 + n) * 64;
            float2 g2 = *(const float2*)&gx[2 * bp];
            *(float2*)&gsm[n][2 * bp] = make_float2(s.x + g2.x, s.y + g2.y);
        }
        __syncthreads();
        if (tid < 256) {
            float gi = gsm[uu][bc], gf = gsm[4 + uu][bc], gg = gsm[8 + uu][bc], go = gsm[12 + uu][bc];
            int u = ub * 4 + uu;
            size_t ci = ((size_t)dir * HH + u) * BB + bc;
            float c = g_cencT[ci];
            c = sigf(gf) * c + sigf(gi) * tanhf(gg);
            float hn = sigf(go) * tanhf(c);
            g_cencT[ci] = c;
            g_hencT[((size_t)(p ^ 1) * 2 + dir) * HH * BB + (size_t)u * BB + bc] = hn;
            g_h[((size_t)s0 * BB + bc) * DHH + dir * HH + u] = hn;
        }
        p ^= 1;
        gsync2(blk, ++gen);
    }
    // ---- fused tail: pre0 = [h|x]@Wmid0+bd (4096 tiles) and wh = h@Wl (1024 tiles) ----
    {
        int hh = tid >> 8;                 // half 0/1
        int t256 = tid & 255;
        float (*As)[68] = (float(*)[68])(dyn + hh * 2432);
        float (*Ws)[68] = (float(*)[68])(dyn + hh * 2432 + 1120);
        for (int i = 0; i < 20; i++) {
            int T = blk * 40 + hh * 20 + i;
            if (T < 4096) {
                gemm_body(As, Ws, t256, g_h, DHH, g_x, nullptr, g_Wmid0, 1024,
                          g_pre0, GD, 1024, nullptr, g_bdp, 1,
                          (T >> 5) * 64, (T & 31) * 64, 1 + hh);
            } else {
                int t2 = T - 4096;
                gemm_body(As, Ws, t256, g_h, DHH, nullptr, nullptr, Wl, DHH,
                          g_wh, DHH, DHH, nullptr, nullptr, 0,
                          (t2 >> 3) * 64, (t2 & 7) * 64, 1 + hh);
            }
        }
    }
}

// ---------------- persistent decoder ----------------
#define SMEM_DEC ((1024*16 + 16*1024) * 4)  // Wsm 64KB + Csm 64KB = 128KB
__global__ void __launch_bounds__(TPB, 1) dec_persist(int l0, int l1) {
    extern __shared__ __align__(16) float dyn[];
    float* Wsm = dyn;                        // [1024][16]
    float* Csm = dyn + 1024 * 16;
    float (*Asm)[64] = (float(*)[64])Csm;
    __shared__ float gsm[16][64];
    __shared__ __align__(16) float hd_s[DHH];
    __shared__ float sc[64];
    __shared__ __align__(16) float c0sm[64], c1sm[64];
    int blk = blockIdx.x, tid = threadIdx.x;
    int half = blk & 1, ab = blk >> 1;
    for (int i = tid; i < 16 * 1024; i += TPB) {
        int r = i >> 10, k = i & 1023;
        Wsm[k * 16 + r] = g_Wcat[((size_t)blk * 16 + r) * 1024 + k];
    }
    __syncthreads();
    int lane = tid & 31, w = tid >> 5;
    int ntile = lane >> 3, btile = lane & 7;
    int kl = tid >> 3, b8 = (tid & 7) << 3;
    int uu = tid >> 6, bc = tid & 63;
    const float* WkA = Wsm + 512 * 16;       // hd half (k 512..1023)
    const float* WkB = Wsm;                  // ctx half (k 0..511)
    unsigned gen = bar_base();
    for (int lvl = l0; lvl < l1; lvl++) {
        const float* pre = (lvl == 0) ? g_pre0 : g_pre1;
        float ohn = g_ohcp[lvl * GD + blk * 16 + (tid >> 5)];
        for (int t = 0; t < SS; t++) {
            // ===== phase A: attention half, then hd-half GEMM =====
            {
                for (int i = tid; i < DHH; i += TPB) hd_s[i] = g_hd[ab * DHH + i];
                __syncthreads();
                for (int it = 0; it < 4; it++) {
                    int s_loc = w * 4 + it;
                    int s = half * 64 + s_loc;
                    const float4* w4 = (const float4*)(g_wh + ((size_t)s * BB + ab) * DHH);
                    const float4* h4 = (const float4*)hd_s;
                    float sum = 0.f;
                    #pragma unroll
                    for (int qq = 0; qq < 4; qq++) {
                        float4 a = w4[lane * 4 + qq];
                        float4 c = h4[lane * 4 + qq];
                        sum += a.x * c.x + a.y * c.y + a.z * c.z + a.w * c.w;
                    }
                    #pragma unroll
                    for (int off = 16; off; off >>= 1) sum += __shfl_xor_sync(0xffffffffu, sum, off);
                    if (lane == 0) sc[s_loc] = sum;
                }
                __syncthreads();
                if (w == 0) {   // single-warp softmax over 64 scores
                    float v0 = sc[lane], v1 = sc[lane + 32];
                    float m = fmaxf(v0, v1);
                    #pragma unroll
                    for (int off = 16; off; off >>= 1) m = fmaxf(m, __shfl_xor_sync(0xffffffffu, m, off));
                    float e0 = __expf(v0 - m), e1 = __expf(v1 - m);
                    float ssum = e0 + e1;
                    #pragma unroll
                    for (int off = 16; off; off >>= 1) ssum += __shfl_xor_sync(0xffffffffu, ssum, off);
                    sc[lane] = e0; sc[lane + 32] = e1;
                    if (lane == 0) { g_attM[ab * 2 + half] = m; g_attS[ab * 2 + half] = ssum; }
                }
                __syncthreads();
                {
                    int d = tid;
                    float acc = 0.f;
                    #pragma unroll 8
                    for (int s_loc = 0; s_loc < 64; s_loc++)
                        acc += sc[s_loc] * g_h[(((size_t)(half * 64 + s_loc)) * BB + ab) * DHH + d];
                    g_ctxP[((size_t)half * DHH + d) * 64 + ab] = acc;
                }
                __syncthreads();
            }
            ull acc[4][4] = {};
            wres_rt<8>(g_hdT, WkA, Asm, w, ntile, btile, kl, b8, acc);
            gsync2(blk, ++gen);
            // ===== phase B: flash-merge + ctx-half GEMM + combine + cell =====
            if (tid < 64) {
                float m0 = g_attM[tid * 2], m1 = g_attM[tid * 2 + 1];
                float M = fmaxf(m0, m1);
                float e0 = __expf(m0 - M), e1 = __expf(m1 - M);
                float den = g_attS[tid * 2] * e0 + g_attS[tid * 2 + 1] * e1;
                c0sm[tid] = e0 / den;
                c1sm[tid] = e1 / den;
            }
            __syncthreads();
            float4 c0a = *(const float4*)&c0sm[b8];
            float4 c0b = *(const float4*)&c0sm[b8 + 4];
            float4 c1a = *(const float4*)&c1sm[b8];
            float4 c1b = *(const float4*)&c1sm[b8 + 4];
            wres_rtm<8>(g_ctxP, g_ctxP + DHH * 64, c0a, c1a, c0b, c1b,
                        WkB, Asm, w, ntile, btile, kl, b8, acc);
            float2 s = kseg_combine(Csm, acc, w, ntile, btile, tid);
            {
                int n = tid >> 5, bp = tid & 31;
                const float* pr = pre + ((size_t)t * GD + blk * 16 + n) * 64;
                float2 p2 = *(const float2*)&pr[2 * bp];
                *(float2*)&gsm[n][2 * bp] = make_float2(s.x + p2.x + ohn, s.y + p2.y + ohn);
            }
            __syncthreads();
            if (tid < 256) {
                float gi = gsm[uu][bc], gf = gsm[4 + uu][bc], gg = gsm[8 + uu][bc], go = gsm[12 + uu][bc];
                int u = blk * 4 + uu;
                size_t ci = (size_t)u * BB + bc;
                float c = g_cdT[ci];
                c = sigf(gf) * c + sigf(gi) * tanhf(gg);
                float hn = sigf(go) * tanhf(c);
                g_cdT[ci] = c;
                g_hdT[ci] = hn;
                g_hd[(size_t)bc * DHH + u] = hn;
                g_dout[(((size_t)lvl * SS + t) * BB + bc) * DHH + u] = hn;
            }
            gsync2(blk, ++gen);
        }
    }
}

// ---------------- output projection ----------------
__global__ void out_proj(const float* __restrict__ W2, const float* __restrict__ b2,
                         float* __restrict__ out) {
    int m = blockIdx.x;
    int lane = threadIdx.x;
    const float* drow = g_dout + (size_t)m * DHH;
    float acc[CC] = {};
    for (int k = lane; k < DHH; k += 32) {
        float d = drow[k];
        #pragma unroll
        for (int c = 0; c < CC; c++) acc[c] += d * W2[c * DHH + k];
    }
    #pragma unroll
    for (int c = 0; c < CC; c++) {
        float v = acc[c];
        #pragma unroll
        for (int off = 16; off; off >>= 1) v += __shfl_xor_sync(0xffffffffu, v, off);
        if (lane == 0) out[(size_t)m * CC + c] = v + b2[c];
    }
}

// ---------------- host ----------------
extern "C" void kernel_launch(void* const* d_in, const int* in_sizes, int n_in,
                              void* d_out, int out_size) {
    const int*   seqs  = (const int*)d_in[0];
    const float* emb   = (const float*)d_in[2];
    const float* Wih_f = (const float*)d_in[3];
    const float* Whh_f = (const float*)d_in[4];
    const float* bih_f = (const float*)d_in[5];
    const float* bhh_f = (const float*)d_in[6];
    const float* Wih_b = (const float*)d_in[7];
    const float* Whh_b = (const float*)d_in[8];
    const float* bih_b = (const float*)d_in[9];
    const float* bhh_b = (const float*)d_in[10];
    const float* Wl    = (const float*)d_in[11];
    const float* Wih_d = (const float*)d_in[12];
    const float* Whh_d = (const float*)d_in[13];
    const float* bih_d = (const float*)d_in[14];
    const float* bhh_d = (const float*)d_in[15];
    const float* W2    = (const float*)d_in[16];
    const float* b2    = (const float*)d_in[17];
    float* out = (float*)d_out;

    cudaFuncSetAttribute(enc_persist, cudaFuncAttributeMaxDynamicSharedMemorySize, SMEM_ENC);
    cudaFuncSetAttribute(dec_persist, cudaFuncAttributeMaxDynamicSharedMemorySize, SMEM_DEC);

    // 0: prep (embed + permute + zero)
    k_prep<<<(PREP_TOTAL + 255) / 256, 256>>>(seqs, emb, Whh_f, Whh_b, Wih_f, Wih_b,
                                              bih_f, bhh_f, bih_b, bhh_b,
                                              Wih_d, Whh_d, bih_d, bhh_d);
    // 1: encoder input GEMMs
    k_encg<<<dim3(SS * BB / 64, G4H / 64, 2), 256>>>();
    // 2: encoder recurrence + fused pre0/wh tail
    enc_persist<<<NBE, TPB, SMEM_ENC>>>(Wl);
    // 3: decoder level 0   <-- ncu capture target
    dec_persist<<<NBD, TPB, SMEM_DEC>>>(0, 1);
    // 4: pre1 = pre0 + (dout0 - h)@Wprev
    k_pre1<<<dim3(SS * BB / 64, GD / 64), 256>>>();
    // 5: decoder levels 1-3
    dec_persist<<<NBD, TPB, SMEM_DEC>>>(1, 4);
    // 6: logits
    out_proj<<<LMAXX * SS * BB, 32>>>(W2, b2, out);
}